// round 13
// baseline (speedup 1.0000x reference)
#include <cuda_runtime.h>
#include <cuda_fp16.h>
#include <math.h>
#include <stdint.h>

#define B_    2
#define S_    2048
#define DM    1024
#define H_    16
#define DH    64
#define DFF   4096
#define MTOK  (B_*S_)      // 4096 token rows

// ---------------- scratch (device globals; no allocation) ----------------
__device__ __half g_q16 [MTOK*DM];
__device__ __half g_k16 [MTOK*DM];
__device__ __half g_wq16[DM*DM];
__device__ __half g_wk16[DM*DM];
__device__ __half g_wv16[DM*DM];
__device__ __half g_w116[(size_t)DFF*DM];
__device__ __half g_w216[(size_t)DM*DFF];
__device__ __half g_Qh  [MTOK*DM];
__device__ __half g_Kh  [MTOK*DM];
__device__ __half g_Vh  [MTOK*DM];
__device__ __half g_Xh  [MTOK*DM];
__device__ __half g_Hh  [(size_t)MTOK*DFF];
__device__ float  g_att [MTOK*DM];
__device__ float  g_x   [MTOK*DM];

// ---------------- helpers -------------------------------------------------
__device__ __forceinline__ void mma_f16(float c[4],
                                        unsigned a0, unsigned a1, unsigned a2, unsigned a3,
                                        unsigned b0, unsigned b1) {
    asm volatile("mma.sync.aligned.m16n8k16.row.col.f32.f16.f16.f32 "
                 "{%0,%1,%2,%3}, {%4,%5,%6,%7}, {%8,%9}, {%0,%1,%2,%3};"
                 : "+f"(c[0]), "+f"(c[1]), "+f"(c[2]), "+f"(c[3])
                 : "r"(a0), "r"(a1), "r"(a2), "r"(a3), "r"(b0), "r"(b1));
}

#define LDSM_X4(r0, r1, r2, r3, addr) \
    asm volatile("ldmatrix.sync.aligned.m8n8.x4.shared.b16 {%0,%1,%2,%3}, [%4];" \
                 : "=r"(r0), "=r"(r1), "=r"(r2), "=r"(r3) : "r"(addr))

#define LDSM_X4T(r0, r1, r2, r3, addr) \
    asm volatile("ldmatrix.sync.aligned.m8n8.x4.trans.shared.b16 {%0,%1,%2,%3}, [%4];" \
                 : "=r"(r0), "=r"(r1), "=r"(r2), "=r"(r3) : "r"(addr))

#define CP_ASYNC16(dst, src) \
    asm volatile("cp.async.cg.shared.global [%0], [%1], 16;" :: "r"(dst), "l"(src))
#define CP_COMMIT() asm volatile("cp.async.commit_group;" ::: "memory")
#define CP_WAIT1()  asm volatile("cp.async.wait_group 1;" ::: "memory")
#define CP_WAIT2()  asm volatile("cp.async.wait_group 2;" ::: "memory")

// pack two floats -> f16x2 register (lo = a, hi = b)
__device__ __forceinline__ unsigned packh2(float a, float b) {
    unsigned r;
    asm("cvt.rn.f16x2.f32 %0, %1, %2;" : "=r"(r) : "f"(b), "f"(a));
    return r;
}

// ---------------- fused fp32 -> fp16 conversion (all 7 tensors) ----------
__global__ __launch_bounds__(256)
void f2h_all(const float4* __restrict__ q,  const float4* __restrict__ k,
             const float4* __restrict__ wq, const float4* __restrict__ wk,
             const float4* __restrict__ wv, const float4* __restrict__ w1,
             const float4* __restrict__ w2,
             uint2* __restrict__ q16,  uint2* __restrict__ k16,
             uint2* __restrict__ wq16, uint2* __restrict__ wk16,
             uint2* __restrict__ wv16, uint2* __restrict__ w116,
             uint2* __restrict__ w216)
{
    const int bx = blockIdx.x;
    const float4* src; uint2* dst; int off;
    if      (bx <  4096) { src = q;  dst = q16;  off = bx; }
    else if (bx <  8192) { src = k;  dst = k16;  off = bx - 4096; }
    else if (bx <  9216) { src = wq; dst = wq16; off = bx - 8192; }
    else if (bx < 10240) { src = wk; dst = wk16; off = bx - 9216; }
    else if (bx < 11264) { src = wv; dst = wv16; off = bx - 10240; }
    else if (bx < 15360) { src = w1; dst = w116; off = bx - 11264; }
    else                 { src = w2; dst = w216; off = bx - 15360; }
    const int i = off * 256 + threadIdx.x;
    float4 v = src[i];
    uint2 o;
    o.x = packh2(v.x, v.y);
    o.y = packh2(v.z, v.w);
    dst[i] = o;
}

// ---------------- fp16 GEMM, NT, 128x256 tile, warp 64x64, cp.async ------
// C[m,n] = sum_k A[m,k]*B[n,k]. 8 warps 2m x 4n, KC=32, 4-stage pipeline.
// EPI: 0 = +bias -> fp16; 1 = gelu(+bias) -> fp16; 2 = +bias+res -> fp32
#define KC32    32
#define HPW     40                        // pitch 40 halves = 80B = 5*16
#define ABYTES  (128 * HPW * 2)           // 10240 B
#define BBYTES  (256 * HPW * 2)           // 20480 B
#define STAGEB  (ABYTES + BBYTES)         // 30720 B
#define NSTG    4
#define GSMEM   (NSTG * STAGEB)           // 122880 B dynamic smem

template<int EPI>
__global__ __launch_bounds__(256, 1)
void gemm16(const __half* __restrict__ A, const __half* __restrict__ Bm,
            const float* __restrict__ bias, void* __restrict__ Cout,
            const float* __restrict__ res, int M, int N, int K)
{
    extern __shared__ char smem[];
    const uint32_t sbase = (uint32_t)__cvta_generic_to_shared(smem);

    const int tid  = threadIdx.x;
    const int m0   = blockIdx.y * 128;
    const int n0   = blockIdx.x * 256;
    const int lane = tid & 31;
    const int w    = tid >> 5;
    const int wm   = (w >> 2) * 64;      // 0 or 64
    const int wn   = (w & 3) * 64;       // 0,64,128,192
    const int g    = lane >> 2;
    const int t    = lane & 3;

    float acc[4][8][4];
    #pragma unroll
    for (int i = 0; i < 4; i++)
        #pragma unroll
        for (int j = 0; j < 8; j++)
            #pragma unroll
            for (int u = 0; u < 4; u++) acc[i][j][u] = 0.f;

    const uint32_t a_frag = sbase + (((uint32_t)(wm + (lane & 15))) * HPW + ((lane >> 4) * 8)) * 2;
    const uint32_t b_frag = sbase + ABYTES + (((uint32_t)(wn + (lane & 7))) * HPW + ((lane >> 3) * 8)) * 2;

    // cp.async staging: A rows srow, srow+64; B rows srow + {0,64,128,192}
    const int srow = tid >> 2;           // 0..63
    const int sgrp = tid & 3;            // 16B group
    const uint32_t sdst = sbase + ((uint32_t)(srow * HPW + sgrp * 8)) * 2;
    const __half* gA = A  + (size_t)(m0 + srow) * K + sgrp * 8;
    const __half* gB = Bm + (size_t)(n0 + srow) * K + sgrp * 8;

    auto issue = [&](int c) {
        const uint32_t so = (uint32_t)(c % NSTG) * STAGEB;
        const int k0 = c * KC32;
        #pragma unroll
        for (int i = 0; i < 2; i++)
            CP_ASYNC16(sdst + so + i * (64 * HPW * 2), gA + (size_t)(i * 64) * K + k0);
        #pragma unroll
        for (int i = 0; i < 4; i++)
            CP_ASYNC16(sdst + so + ABYTES + i * (64 * HPW * 2), gB + (size_t)(i * 64) * K + k0);
    };
    auto compute = [&](int st) {
        const uint32_t bo = (uint32_t)st * STAGEB;
        unsigned bq[8][4];
        #pragma unroll
        for (int nt = 0; nt < 8; nt++)
            LDSM_X4(bq[nt][0], bq[nt][1], bq[nt][2], bq[nt][3],
                    b_frag + bo + nt * (8 * HPW * 2));
        #pragma unroll
        for (int kh = 0; kh < 2; kh++) {
            unsigned aq[4][4];
            #pragma unroll
            for (int mt = 0; mt < 4; mt++)
                LDSM_X4(aq[mt][0], aq[mt][1], aq[mt][2], aq[mt][3],
                        a_frag + bo + mt * (16 * HPW * 2) + kh * 32);
            #pragma unroll
            for (int mt = 0; mt < 4; mt++)
                #pragma unroll
                for (int nt = 0; nt < 8; nt++)
                    mma_f16(acc[mt][nt], aq[mt][0], aq[mt][1], aq[mt][2], aq[mt][3],
                            bq[nt][kh * 2], bq[nt][kh * 2 + 1]);
        }
    };

    const int NC = K / KC32;
    issue(0); CP_COMMIT();
    if (NC > 1) issue(1);
    CP_COMMIT();
    if (NC > 2) issue(2);
    CP_COMMIT();
    for (int c = 0; c < NC; c++) {
        CP_WAIT2();                 // stage c landed (2 younger groups pending)
        __syncthreads();
        if (c + 3 < NC) issue(c + 3);
        CP_COMMIT();                // uniform group accounting
        compute(c % NSTG);
    }

    // epilogue
    #pragma unroll
    for (int mt = 0; mt < 4; mt++) {
        #pragma unroll
        for (int half = 0; half < 2; half++) {
            const int row = m0 + wm + mt * 16 + g + half * 8;
            #pragma unroll
            for (int nt = 0; nt < 8; nt++) {
                const int col = n0 + wn + nt * 8 + 2 * t;
                float v0 = acc[mt][nt][half * 2 + 0] + bias[col];
                float v1 = acc[mt][nt][half * 2 + 1] + bias[col + 1];
                if (EPI == 1) {
                    v0 = 0.5f * v0 * (1.0f + erff(v0 * 0.70710678118654752f));
                    v1 = 0.5f * v1 * (1.0f + erff(v1 * 0.70710678118654752f));
                }
                if (EPI == 2) {
                    v0 += res[(size_t)row * N + col];
                    v1 += res[(size_t)row * N + col + 1];
                    float2 o; o.x = v0; o.y = v1;
                    *(float2*)&((float*)Cout)[(size_t)row * N + col] = o;
                } else {
                    *(unsigned*)&((__half*)Cout)[(size_t)row * N + col] = packh2(v0, v1);
                }
            }
        }
    }
}

// ---------------- fp16 tensor-core causal flash attention (R11) ----------
#define AP 72
#define ATILE (64 * AP)   // halves per tile

__global__ __launch_bounds__(128, 3)
void attn_tc(const __half* __restrict__ Q, const __half* __restrict__ K,
             const __half* __restrict__ V, float* __restrict__ O,
             const int* __restrict__ use_mask)
{
    __shared__ __half Ks[2][ATILE];
    __shared__ __half Vs[2][ATILE];

    const int tid  = threadIdx.x;
    const int lane = tid & 31;
    const int w    = tid >> 5;
    const int g    = lane >> 2;
    const int t    = lane & 3;
    const int qb   = (gridDim.x - 1) - blockIdx.x;
    const int h    = blockIdx.y;
    const int b    = blockIdx.z;
    const int q0   = qb * 64;
    const int causal = use_mask[0];
    const int row0 = q0 + w * 16 + g;

    unsigned qf[4][4];
    {
        const __half* qp  = Q + ((size_t)(b * S_ + row0)) * DM + h * DH;
        const __half* qp8 = qp + 8 * DM;
        #pragma unroll
        for (int ks = 0; ks < 4; ks++) {
            const int c = ks * 16 + 2 * t;
            qf[ks][0] = *(const unsigned*)&qp [c];
            qf[ks][1] = *(const unsigned*)&qp8[c];
            qf[ks][2] = *(const unsigned*)&qp [c + 8];
            qf[ks][3] = *(const unsigned*)&qp8[c + 8];
        }
    }

    const uint32_t sK = (uint32_t)__cvta_generic_to_shared(&Ks[0][0]);
    const uint32_t sV = (uint32_t)__cvta_generic_to_shared(&Vs[0][0]);
    const uint32_t k_frag = sK + (((uint32_t)(lane & 7))  * AP + ((lane >> 3) * 8)) * 2;
    const uint32_t v_frag = sV + (((uint32_t)(lane & 15)) * AP + ((lane >> 4) * 8)) * 2;

    const int sr = tid >> 3;
    const int sg = tid & 7;
    const uint32_t kdst = sK + ((uint32_t)(sr * AP + sg * 8)) * 2;
    const uint32_t vdst = sV + ((uint32_t)(sr * AP + sg * 8)) * 2;
    const __half* ksrc = K + ((size_t)(b * S_) + sr) * DM + h * DH + sg * 8;
    const __half* vsrc = V + ((size_t)(b * S_) + sr) * DM + h * DH + sg * 8;

    auto issue_tile = [&](int kb, int buf) {
        const uint32_t bo = (uint32_t)buf * (ATILE * 2);
        const size_t go = (size_t)(kb * 64) * DM;
        #pragma unroll
        for (int i = 0; i < 4; i++) {
            const uint32_t so = (uint32_t)(i * 16 * AP) * 2;
            const size_t gg = go + (size_t)(i * 16) * DM;
            CP_ASYNC16(kdst + bo + so, ksrc + gg);
            CP_ASYNC16(vdst + bo + so, vsrc + gg);
        }
    };

    float m0 = -INFINITY, m1 = -INFINITY, l0 = 0.f, l1 = 0.f;
    float oacc[8][4];
    #pragma unroll
    for (int nt = 0; nt < 8; nt++)
        #pragma unroll
        for (int u = 0; u < 4; u++) oacc[nt][u] = 0.f;

    const int nkb = causal ? (qb + 1) : (S_ / 64);

    issue_tile(0, 0);
    CP_COMMIT();
    if (nkb > 1) issue_tile(1, 1);
    CP_COMMIT();

    for (int kb = 0; kb < nkb; kb++) {
        const int buf = kb & 1;
        CP_WAIT1();
        __syncthreads();

        const uint32_t bo = (uint32_t)buf * (ATILE * 2);

        float sa[8][4];
        #pragma unroll
        for (int nt = 0; nt < 8; nt++)
            #pragma unroll
            for (int u = 0; u < 4; u++) sa[nt][u] = 0.f;

        #pragma unroll
        for (int nt = 0; nt < 8; nt++) {
            unsigned kq[8];
            LDSM_X4(kq[0], kq[1], kq[2], kq[3], k_frag + bo + (nt * 8 * AP) * 2);
            LDSM_X4(kq[4], kq[5], kq[6], kq[7], k_frag + bo + (nt * 8 * AP) * 2 + 64);
            #pragma unroll
            for (int ks = 0; ks < 4; ks++)
                mma_f16(sa[nt], qf[ks][0], qf[ks][1], qf[ks][2], qf[ks][3],
                        kq[ks * 2], kq[ks * 2 + 1]);
        }

        const bool mask_tile = causal && (kb == qb);
        float smax0 = -INFINITY, smax1 = -INFINITY;
        #pragma unroll
        for (int nt = 0; nt < 8; nt++) {
            const int col = kb * 64 + nt * 8 + 2 * t;
            sa[nt][0] *= 0.125f; sa[nt][1] *= 0.125f;
            sa[nt][2] *= 0.125f; sa[nt][3] *= 0.125f;
            if (mask_tile) {
                if (col     > row0)     sa[nt][0] = -1e9f;
                if (col + 1 > row0)     sa[nt][1] = -1e9f;
                if (col     > row0 + 8) sa[nt][2] = -1e9f;
                if (col + 1 > row0 + 8) sa[nt][3] = -1e9f;
            }
            smax0 = fmaxf(smax0, fmaxf(sa[nt][0], sa[nt][1]));
            smax1 = fmaxf(smax1, fmaxf(sa[nt][2], sa[nt][3]));
        }
        smax0 = fmaxf(smax0, __shfl_xor_sync(0xffffffffu, smax0, 1));
        smax0 = fmaxf(smax0, __shfl_xor_sync(0xffffffffu, smax0, 2));
        smax1 = fmaxf(smax1, __shfl_xor_sync(0xffffffffu, smax1, 1));
        smax1 = fmaxf(smax1, __shfl_xor_sync(0xffffffffu, smax1, 2));

        const float m0n = fmaxf(m0, smax0);
        const float m1n = fmaxf(m1, smax1);
        const float cr0 = __expf(m0 - m0n);
        const float cr1 = __expf(m1 - m1n);
        m0 = m0n; m1 = m1n;

        float ls0 = 0.f, ls1 = 0.f;
        #pragma unroll
        for (int nt = 0; nt < 8; nt++) {
            sa[nt][0] = __expf(sa[nt][0] - m0n);
            sa[nt][1] = __expf(sa[nt][1] - m0n);
            sa[nt][2] = __expf(sa[nt][2] - m1n);
            sa[nt][3] = __expf(sa[nt][3] - m1n);
            ls0 += sa[nt][0] + sa[nt][1];
            ls1 += sa[nt][2] + sa[nt][3];
        }
        ls0 += __shfl_xor_sync(0xffffffffu, ls0, 1);
        ls0 += __shfl_xor_sync(0xffffffffu, ls0, 2);
        ls1 += __shfl_xor_sync(0xffffffffu, ls1, 1);
        ls1 += __shfl_xor_sync(0xffffffffu, ls1, 2);
        l0 = l0 * cr0 + ls0;
        l1 = l1 * cr1 + ls1;

        #pragma unroll
        for (int nt = 0; nt < 8; nt++) {
            oacc[nt][0] *= cr0; oacc[nt][1] *= cr0;
            oacc[nt][2] *= cr1; oacc[nt][3] *= cr1;
        }

        #pragma unroll
        for (int ks = 0; ks < 4; ks++) {
            const unsigned a0 = packh2(sa[2*ks  ][0], sa[2*ks  ][1]);
            const unsigned a1 = packh2(sa[2*ks  ][2], sa[2*ks  ][3]);
            const unsigned a2 = packh2(sa[2*ks+1][0], sa[2*ks+1][1]);
            const unsigned a3 = packh2(sa[2*ks+1][2], sa[2*ks+1][3]);
            #pragma unroll
            for (int dg = 0; dg < 4; dg++) {
                unsigned v0, v1, v2, v3;
                LDSM_X4T(v0, v1, v2, v3, v_frag + bo + (ks * 16 * AP + dg * 16) * 2);
                mma_f16(oacc[2*dg    ], a0, a1, a2, a3, v0, v1);
                mma_f16(oacc[2*dg + 1], a0, a1, a2, a3, v2, v3);
            }
        }

        __syncthreads();
        if (kb + 2 < nkb) issue_tile(kb + 2, buf);
        CP_COMMIT();
    }

    const float inv0 = 1.f / l0;
    const float inv1 = 1.f / l1;
    float* op = O + ((size_t)(b * S_ + row0)) * DM + h * DH;
    #pragma unroll
    for (int nt = 0; nt < 8; nt++) {
        float2 v;
        v.x = oacc[nt][0] * inv0; v.y = oacc[nt][1] * inv0;
        *(float2*)&op[nt * 8 + 2 * t] = v;
        v.x = oacc[nt][2] * inv1; v.y = oacc[nt][3] * inv1;
        *(float2*)&op[(size_t)8 * DM + nt * 8 + 2 * t] = v;
    }
}

// ---------------- residual add + layernorm (fp32 out + fp16 copy) --------
__global__ __launch_bounds__(256)
void ln_kernel(const float* __restrict__ att, const float* __restrict__ resid,
               const float* __restrict__ g, const float* __restrict__ bt,
               float* __restrict__ xout, __half* __restrict__ xh)
{
    const int row = blockIdx.x;
    const int tid = threadIdx.x;

    float4 a = *(const float4*)&att  [(size_t)row * DM + tid * 4];
    float4 r = *(const float4*)&resid[(size_t)row * DM + tid * 4];
    float4 v;
    v.x = a.x + r.x; v.y = a.y + r.y; v.z = a.z + r.z; v.w = a.w + r.w;

    float s1 = v.x + v.y + v.z + v.w;
    float s2 = v.x*v.x + v.y*v.y + v.z*v.z + v.w*v.w;

    __shared__ float sh1[8], sh2[8];
    #pragma unroll
    for (int o = 16; o > 0; o >>= 1) {
        s1 += __shfl_xor_sync(0xffffffffu, s1, o);
        s2 += __shfl_xor_sync(0xffffffffu, s2, o);
    }
    if ((tid & 31) == 0) { sh1[tid >> 5] = s1; sh2[tid >> 5] = s2; }
    __syncthreads();
    float t1 = 0.f, t2 = 0.f;
    #pragma unroll
    for (int i = 0; i < 8; i++) { t1 += sh1[i]; t2 += sh2[i]; }

    const float mu  = t1 * (1.0f / DM);
    const float var = t2 * (1.0f / DM) - mu * mu;
    const float rs  = rsqrtf(var + 1e-5f);

    float4 gg = *(const float4*)&g [tid * 4];
    float4 bb = *(const float4*)&bt[tid * 4];
    float4 o;
    o.x = (v.x - mu) * rs * gg.x + bb.x;
    o.y = (v.y - mu) * rs * gg.y + bb.y;
    o.z = (v.z - mu) * rs * gg.z + bb.z;
    o.w = (v.w - mu) * rs * gg.w + bb.w;
    *(float4*)&xout[(size_t)row * DM + tid * 4] = o;
    uint2 hh;
    hh.x = packh2(o.x, o.y);
    hh.y = packh2(o.z, o.w);
    *(uint2*)&xh[(size_t)row * DM + tid * 4] = hh;
}

// ---------------- launch ---------------------------------------------------
extern "C" void kernel_launch(void* const* d_in, const int* in_sizes, int n_in,
                              void* d_out, int out_size)
{
    const float* q    = (const float*)d_in[0];
    const float* k    = (const float*)d_in[1];
    const float* Wq   = (const float*)d_in[2];
    const float* bq   = (const float*)d_in[3];
    const float* Wk   = (const float*)d_in[4];
    const float* bk   = (const float*)d_in[5];
    const float* Wv   = (const float*)d_in[6];
    const float* bv   = (const float*)d_in[7];
    const float* W1   = (const float*)d_in[8];
    const float* b1   = (const float*)d_in[9];
    const float* W2   = (const float*)d_in[10];
    const float* b2   = (const float*)d_in[11];
    const float* ln_g = (const float*)d_in[12];
    const float* ln_b = (const float*)d_in[13];
    const int*   msk  = (const int*)d_in[14];

    __half *q16, *k16, *wq16, *wk16, *wv16, *w116, *w216, *Qh, *Kh, *Vh, *Xh, *Hh;
    float *Ab, *Xb;
    cudaGetSymbolAddress((void**)&q16,  g_q16);
    cudaGetSymbolAddress((void**)&k16,  g_k16);
    cudaGetSymbolAddress((void**)&wq16, g_wq16);
    cudaGetSymbolAddress((void**)&wk16, g_wk16);
    cudaGetSymbolAddress((void**)&wv16, g_wv16);
    cudaGetSymbolAddress((void**)&w116, g_w116);
    cudaGetSymbolAddress((void**)&w216, g_w216);
    cudaGetSymbolAddress((void**)&Qh,   g_Qh);
    cudaGetSymbolAddress((void**)&Kh,   g_Kh);
    cudaGetSymbolAddress((void**)&Vh,   g_Vh);
    cudaGetSymbolAddress((void**)&Xh,   g_Xh);
    cudaGetSymbolAddress((void**)&Hh,   g_Hh);
    cudaGetSymbolAddress((void**)&Ab,   g_att);
    cudaGetSymbolAddress((void**)&Xb,   g_x);

    cudaFuncSetAttribute(gemm16<0>, cudaFuncAttributeMaxDynamicSharedMemorySize, GSMEM);
    cudaFuncSetAttribute(gemm16<1>, cudaFuncAttributeMaxDynamicSharedMemorySize, GSMEM);
    cudaFuncSetAttribute(gemm16<2>, cudaFuncAttributeMaxDynamicSharedMemorySize, GSMEM);

    // fused fp32 -> fp16 conversion pass
    f2h_all<<<19456, 256>>>((const float4*)q,  (const float4*)k,
                            (const float4*)Wq, (const float4*)Wk,
                            (const float4*)Wv, (const float4*)W1,
                            (const float4*)W2,
                            (uint2*)q16, (uint2*)k16, (uint2*)wq16,
                            (uint2*)wk16, (uint2*)wv16, (uint2*)w116,
                            (uint2*)w216);

    // QKV projections (fp16 out)
    gemm16<0><<<dim3(DM / 256, MTOK / 128), 256, GSMEM>>>(q16, wq16, bq, Qh, nullptr, MTOK, DM, DM);
    gemm16<0><<<dim3(DM / 256, MTOK / 128), 256, GSMEM>>>(k16, wk16, bk, Kh, nullptr, MTOK, DM, DM);
    gemm16<0><<<dim3(DM / 256, MTOK / 128), 256, GSMEM>>>(k16, wv16, bv, Vh, nullptr, MTOK, DM, DM);

    // causal attention (fp16 in, fp32 out)
    attn_tc<<<dim3(S_ / 64, H_, B_), 128>>>(Qh, Kh, Vh, Ab, msk);

    // residual + layernorm (fp32 + fp16 outputs)
    ln_kernel<<<MTOK, 256>>>(Ab, q, ln_g, ln_b, Xb, Xh);

    // FFN
    gemm16<1><<<dim3(DFF / 256, MTOK / 128), 256, GSMEM>>>(Xh, w116, b1, Hh, nullptr, MTOK, DFF, DM);
    gemm16<2><<<dim3(DM / 256, MTOK / 128), 256, GSMEM>>>(Hh, w216, b2, d_out, Xb, MTOK, DM, DFF);
}

// round 14
// speedup vs baseline: 1.1588x; 1.1588x over previous
#include <cuda_runtime.h>
#include <cuda_fp16.h>
#include <math.h>
#include <stdint.h>

#define B_    2
#define S_    2048
#define DM    1024
#define H_    16
#define DH    64
#define DFF   4096
#define MTOK  (B_*S_)      // 4096 token rows

// ---------------- scratch (device globals; no allocation) ----------------
__device__ __half g_q16 [MTOK*DM];
__device__ __half g_k16 [MTOK*DM];
__device__ __half g_wq16[DM*DM];
__device__ __half g_wk16[DM*DM];
__device__ __half g_wv16[DM*DM];
__device__ __half g_w116[(size_t)DFF*DM];
__device__ __half g_w216[(size_t)DM*DFF];
__device__ __half g_Qh  [MTOK*DM];
__device__ __half g_Kh  [MTOK*DM];
__device__ __half g_Vh  [MTOK*DM];
__device__ __half g_Xh  [MTOK*DM];
__device__ __half g_Hh  [(size_t)MTOK*DFF];
__device__ float  g_att [MTOK*DM];
__device__ float  g_x   [MTOK*DM];

// ---------------- helpers -------------------------------------------------
__device__ __forceinline__ void mma_f16(float c[4],
                                        unsigned a0, unsigned a1, unsigned a2, unsigned a3,
                                        unsigned b0, unsigned b1) {
    asm volatile("mma.sync.aligned.m16n8k16.row.col.f32.f16.f16.f32 "
                 "{%0,%1,%2,%3}, {%4,%5,%6,%7}, {%8,%9}, {%0,%1,%2,%3};"
                 : "+f"(c[0]), "+f"(c[1]), "+f"(c[2]), "+f"(c[3])
                 : "r"(a0), "r"(a1), "r"(a2), "r"(a3), "r"(b0), "r"(b1));
}

#define LDSM_X4(r0, r1, r2, r3, addr) \
    asm volatile("ldmatrix.sync.aligned.m8n8.x4.shared.b16 {%0,%1,%2,%3}, [%4];" \
                 : "=r"(r0), "=r"(r1), "=r"(r2), "=r"(r3) : "r"(addr))

#define LDSM_X4T(r0, r1, r2, r3, addr) \
    asm volatile("ldmatrix.sync.aligned.m8n8.x4.trans.shared.b16 {%0,%1,%2,%3}, [%4];" \
                 : "=r"(r0), "=r"(r1), "=r"(r2), "=r"(r3) : "r"(addr))

#define CP_ASYNC16(dst, src) \
    asm volatile("cp.async.cg.shared.global [%0], [%1], 16;" :: "r"(dst), "l"(src))
#define CP_COMMIT() asm volatile("cp.async.commit_group;" ::: "memory")
#define CP_WAIT1()  asm volatile("cp.async.wait_group 1;" ::: "memory")

// pack two floats -> f16x2 register (lo = a, hi = b)
__device__ __forceinline__ unsigned packh2(float a, float b) {
    unsigned r;
    asm("cvt.rn.f16x2.f32 %0, %1, %2;" : "=r"(r) : "f"(b), "f"(a));
    return r;
}

// ---------------- fused fp32 -> fp16 conversion (all 7 tensors) ----------
__global__ __launch_bounds__(256)
void f2h_all(const float4* __restrict__ q,  const float4* __restrict__ k,
             const float4* __restrict__ wq, const float4* __restrict__ wk,
             const float4* __restrict__ wv, const float4* __restrict__ w1,
             const float4* __restrict__ w2,
             uint2* __restrict__ q16,  uint2* __restrict__ k16,
             uint2* __restrict__ wq16, uint2* __restrict__ wk16,
             uint2* __restrict__ wv16, uint2* __restrict__ w116,
             uint2* __restrict__ w216)
{
    const int bx = blockIdx.x;
    const float4* src; uint2* dst; int off;
    if      (bx <  4096) { src = q;  dst = q16;  off = bx; }
    else if (bx <  8192) { src = k;  dst = k16;  off = bx - 4096; }
    else if (bx <  9216) { src = wq; dst = wq16; off = bx - 8192; }
    else if (bx < 10240) { src = wk; dst = wk16; off = bx - 9216; }
    else if (bx < 11264) { src = wv; dst = wv16; off = bx - 10240; }
    else if (bx < 15360) { src = w1; dst = w116; off = bx - 11264; }
    else                 { src = w2; dst = w216; off = bx - 15360; }
    const int i = off * 256 + threadIdx.x;
    float4 v = src[i];
    uint2 o;
    o.x = packh2(v.x, v.y);
    o.y = packh2(v.z, v.w);
    dst[i] = o;
}

// ---------------- fp16 GEMM core (R12 config): 128x128, cp.async 3-stage --
#define KC32   32
#define HPW    40                        // pitch 40 halves = 80B = 5*16
#define ABYTES (128 * HPW * 2)           // 10240 B per operand tile
#define STAGEB (2 * ABYTES)              // 20480 B per stage (A + B)
#define NSTG   3
#define GSMEM  (NSTG * STAGEB)           // 61440 B dynamic smem

// mainloop + epilogue body shared by gemm16 and gemm_qkv
template<int EPI>
__device__ __forceinline__
void gemm_body(const __half* __restrict__ A, const __half* __restrict__ Bm,
               const float* __restrict__ bias, void* __restrict__ Cout,
               const float* __restrict__ res, int M, int N, int K,
               int m0, int n0, char* smem)
{
    const uint32_t sbase = (uint32_t)__cvta_generic_to_shared(smem);
    const int tid  = threadIdx.x;
    const int lane = tid & 31;
    const int w    = tid >> 5;
    const int wm   = (w >> 2) * 64;
    const int wn   = (w & 3) * 32;
    const int g    = lane >> 2;
    const int t    = lane & 3;

    float acc[4][4][4];
    #pragma unroll
    for (int i = 0; i < 4; i++)
        #pragma unroll
        for (int j = 0; j < 4; j++)
            #pragma unroll
            for (int u = 0; u < 4; u++) acc[i][j][u] = 0.f;

    const uint32_t a_frag = sbase + (((uint32_t)(wm + (lane & 15))) * HPW + ((lane >> 4) * 8)) * 2;
    const uint32_t b_frag = sbase + ABYTES + (((uint32_t)(wn + (lane & 7))) * HPW + ((lane >> 3) * 8)) * 2;

    const int srow = tid >> 2;
    const int sgrp = tid & 3;
    const uint32_t sdst = sbase + ((uint32_t)(srow * HPW + sgrp * 8)) * 2;
    const __half* gA = A  + (size_t)(m0 + srow) * K + sgrp * 8;
    const __half* gB = Bm + (size_t)(n0 + srow) * K + sgrp * 8;

    auto issue = [&](int c) {
        const uint32_t so = (uint32_t)(c % NSTG) * STAGEB;
        const int k0 = c * KC32;
        CP_ASYNC16(sdst + so,                         gA + k0);
        CP_ASYNC16(sdst + so + 64 * HPW * 2,          gA + (size_t)64 * K + k0);
        CP_ASYNC16(sdst + so + ABYTES,                gB + k0);
        CP_ASYNC16(sdst + so + ABYTES + 64 * HPW * 2, gB + (size_t)64 * K + k0);
    };
    auto compute = [&](int st) {
        const uint32_t bo = (uint32_t)st * STAGEB;
        unsigned bq[4][4];
        #pragma unroll
        for (int nt = 0; nt < 4; nt++)
            LDSM_X4(bq[nt][0], bq[nt][1], bq[nt][2], bq[nt][3],
                    b_frag + bo + nt * (8 * HPW * 2));
        #pragma unroll
        for (int kh = 0; kh < 2; kh++) {
            unsigned aq[4][4];
            #pragma unroll
            for (int mt = 0; mt < 4; mt++)
                LDSM_X4(aq[mt][0], aq[mt][1], aq[mt][2], aq[mt][3],
                        a_frag + bo + mt * (16 * HPW * 2) + kh * 32);
            #pragma unroll
            for (int mt = 0; mt < 4; mt++)
                #pragma unroll
                for (int nt = 0; nt < 4; nt++)
                    mma_f16(acc[mt][nt], aq[mt][0], aq[mt][1], aq[mt][2], aq[mt][3],
                            bq[nt][kh * 2], bq[nt][kh * 2 + 1]);
        }
    };

    const int NC = K / KC32;
    issue(0); CP_COMMIT();
    if (NC > 1) issue(1);
    CP_COMMIT();
    for (int c = 0; c < NC; c++) {
        CP_WAIT1();
        __syncthreads();
        if (c + 2 < NC) issue(c + 2);
        CP_COMMIT();
        compute(c % NSTG);
    }

    #pragma unroll
    for (int mt = 0; mt < 4; mt++) {
        #pragma unroll
        for (int half = 0; half < 2; half++) {
            const int row = m0 + wm + mt * 16 + g + half * 8;
            #pragma unroll
            for (int nt = 0; nt < 4; nt++) {
                const int col = n0 + wn + nt * 8 + 2 * t;
                float v0 = acc[mt][nt][half * 2 + 0] + bias[col];
                float v1 = acc[mt][nt][half * 2 + 1] + bias[col + 1];
                if (EPI == 1) {
                    v0 = 0.5f * v0 * (1.0f + erff(v0 * 0.70710678118654752f));
                    v1 = 0.5f * v1 * (1.0f + erff(v1 * 0.70710678118654752f));
                }
                if (EPI == 2) {
                    v0 += res[(size_t)row * N + col];
                    v1 += res[(size_t)row * N + col + 1];
                    float2 o; o.x = v0; o.y = v1;
                    *(float2*)&((float*)Cout)[(size_t)row * N + col] = o;
                } else {
                    *(unsigned*)&((__half*)Cout)[(size_t)row * N + col] = packh2(v0, v1);
                }
            }
        }
    }
}

template<int EPI>
__global__ __launch_bounds__(256, 2)
void gemm16(const __half* __restrict__ A, const __half* __restrict__ Bm,
            const float* __restrict__ bias, void* __restrict__ Cout,
            const float* __restrict__ res, int M, int N, int K)
{
    extern __shared__ char smem[];
    gemm_body<EPI>(A, Bm, bias, Cout, res, M, N, K,
                   blockIdx.y * 128, blockIdx.x * 128, smem);
}

// merged QKV projection: grid.z selects {q16*Wq->Qh, k16*Wk->Kh, k16*Wv->Vh}
__global__ __launch_bounds__(256, 2)
void gemm_qkv(const __half* __restrict__ q16, const __half* __restrict__ k16,
              const __half* __restrict__ wq,  const __half* __restrict__ wk,
              const __half* __restrict__ wv,
              const float* __restrict__ bq,   const float* __restrict__ bk,
              const float* __restrict__ bv,
              __half* __restrict__ Qh, __half* __restrict__ Kh,
              __half* __restrict__ Vh)
{
    extern __shared__ char smem[];
    const int z = blockIdx.z;
    const __half* A  = (z == 0) ? q16 : k16;
    const __half* Bm = (z == 0) ? wq : (z == 1 ? wk : wv);
    const float*  bs = (z == 0) ? bq : (z == 1 ? bk : bv);
    __half*       C  = (z == 0) ? Qh : (z == 1 ? Kh : Vh);
    gemm_body<0>(A, Bm, bs, C, nullptr, MTOK, DM, DM,
                 blockIdx.y * 128, blockIdx.x * 128, smem);
}

// ---------------- fp16 tensor-core causal flash attention (R11/R12) ------
#define AP 72
#define ATILE (64 * AP)   // halves per tile

__global__ __launch_bounds__(128, 3)
void attn_tc(const __half* __restrict__ Q, const __half* __restrict__ K,
             const __half* __restrict__ V, float* __restrict__ O,
             const int* __restrict__ use_mask)
{
    __shared__ __half Ks[2][ATILE];
    __shared__ __half Vs[2][ATILE];

    const int tid  = threadIdx.x;
    const int lane = tid & 31;
    const int w    = tid >> 5;
    const int g    = lane >> 2;
    const int t    = lane & 3;
    const int qb   = (gridDim.x - 1) - blockIdx.x;
    const int h    = blockIdx.y;
    const int b    = blockIdx.z;
    const int q0   = qb * 64;
    const int causal = use_mask[0];
    const int row0 = q0 + w * 16 + g;

    unsigned qf[4][4];
    {
        const __half* qp  = Q + ((size_t)(b * S_ + row0)) * DM + h * DH;
        const __half* qp8 = qp + 8 * DM;
        #pragma unroll
        for (int ks = 0; ks < 4; ks++) {
            const int c = ks * 16 + 2 * t;
            qf[ks][0] = *(const unsigned*)&qp [c];
            qf[ks][1] = *(const unsigned*)&qp8[c];
            qf[ks][2] = *(const unsigned*)&qp [c + 8];
            qf[ks][3] = *(const unsigned*)&qp8[c + 8];
        }
    }

    const uint32_t sK = (uint32_t)__cvta_generic_to_shared(&Ks[0][0]);
    const uint32_t sV = (uint32_t)__cvta_generic_to_shared(&Vs[0][0]);
    const uint32_t k_frag = sK + (((uint32_t)(lane & 7))  * AP + ((lane >> 3) * 8)) * 2;
    const uint32_t v_frag = sV + (((uint32_t)(lane & 15)) * AP + ((lane >> 4) * 8)) * 2;

    const int sr = tid >> 3;
    const int sg = tid & 7;
    const uint32_t kdst = sK + ((uint32_t)(sr * AP + sg * 8)) * 2;
    const uint32_t vdst = sV + ((uint32_t)(sr * AP + sg * 8)) * 2;
    const __half* ksrc = K + ((size_t)(b * S_) + sr) * DM + h * DH + sg * 8;
    const __half* vsrc = V + ((size_t)(b * S_) + sr) * DM + h * DH + sg * 8;

    auto issue_tile = [&](int kb, int buf) {
        const uint32_t bo = (uint32_t)buf * (ATILE * 2);
        const size_t go = (size_t)(kb * 64) * DM;
        #pragma unroll
        for (int i = 0; i < 4; i++) {
            const uint32_t so = (uint32_t)(i * 16 * AP) * 2;
            const size_t gg = go + (size_t)(i * 16) * DM;
            CP_ASYNC16(kdst + bo + so, ksrc + gg);
            CP_ASYNC16(vdst + bo + so, vsrc + gg);
        }
    };

    float m0 = -INFINITY, m1 = -INFINITY, l0 = 0.f, l1 = 0.f;
    float oacc[8][4];
    #pragma unroll
    for (int nt = 0; nt < 8; nt++)
        #pragma unroll
        for (int u = 0; u < 4; u++) oacc[nt][u] = 0.f;

    const int nkb = causal ? (qb + 1) : (S_ / 64);

    issue_tile(0, 0);
    CP_COMMIT();
    if (nkb > 1) issue_tile(1, 1);
    CP_COMMIT();

    for (int kb = 0; kb < nkb; kb++) {
        const int buf = kb & 1;
        CP_WAIT1();
        __syncthreads();

        const uint32_t bo = (uint32_t)buf * (ATILE * 2);

        float sa[8][4];
        #pragma unroll
        for (int nt = 0; nt < 8; nt++)
            #pragma unroll
            for (int u = 0; u < 4; u++) sa[nt][u] = 0.f;

        #pragma unroll
        for (int nt = 0; nt < 8; nt++) {
            unsigned kq[8];
            LDSM_X4(kq[0], kq[1], kq[2], kq[3], k_frag + bo + (nt * 8 * AP) * 2);
            LDSM_X4(kq[4], kq[5], kq[6], kq[7], k_frag + bo + (nt * 8 * AP) * 2 + 64);
            #pragma unroll
            for (int ks = 0; ks < 4; ks++)
                mma_f16(sa[nt], qf[ks][0], qf[ks][1], qf[ks][2], qf[ks][3],
                        kq[ks * 2], kq[ks * 2 + 1]);
        }

        const bool mask_tile = causal && (kb == qb);
        float smax0 = -INFINITY, smax1 = -INFINITY;
        #pragma unroll
        for (int nt = 0; nt < 8; nt++) {
            const int col = kb * 64 + nt * 8 + 2 * t;
            sa[nt][0] *= 0.125f; sa[nt][1] *= 0.125f;
            sa[nt][2] *= 0.125f; sa[nt][3] *= 0.125f;
            if (mask_tile) {
                if (col     > row0)     sa[nt][0] = -1e9f;
                if (col + 1 > row0)     sa[nt][1] = -1e9f;
                if (col     > row0 + 8) sa[nt][2] = -1e9f;
                if (col + 1 > row0 + 8) sa[nt][3] = -1e9f;
            }
            smax0 = fmaxf(smax0, fmaxf(sa[nt][0], sa[nt][1]));
            smax1 = fmaxf(smax1, fmaxf(sa[nt][2], sa[nt][3]));
        }
        smax0 = fmaxf(smax0, __shfl_xor_sync(0xffffffffu, smax0, 1));
        smax0 = fmaxf(smax0, __shfl_xor_sync(0xffffffffu, smax0, 2));
        smax1 = fmaxf(smax1, __shfl_xor_sync(0xffffffffu, smax1, 1));
        smax1 = fmaxf(smax1, __shfl_xor_sync(0xffffffffu, smax1, 2));

        const float m0n = fmaxf(m0, smax0);
        const float m1n = fmaxf(m1, smax1);
        const float cr0 = __expf(m0 - m0n);
        const float cr1 = __expf(m1 - m1n);
        m0 = m0n; m1 = m1n;

        float ls0 = 0.f, ls1 = 0.f;
        #pragma unroll
        for (int nt = 0; nt < 8; nt++) {
            sa[nt][0] = __expf(sa[nt][0] - m0n);
            sa[nt][1] = __expf(sa[nt][1] - m0n);
            sa[nt][2] = __expf(sa[nt][2] - m1n);
            sa[nt][3] = __expf(sa[nt][3] - m1n);
            ls0 += sa[nt][0] + sa[nt][1];
            ls1 += sa[nt][2] + sa[nt][3];
        }
        ls0 += __shfl_xor_sync(0xffffffffu, ls0, 1);
        ls0 += __shfl_xor_sync(0xffffffffu, ls0, 2);
        ls1 += __shfl_xor_sync(0xffffffffu, ls1, 1);
        ls1 += __shfl_xor_sync(0xffffffffu, ls1, 2);
        l0 = l0 * cr0 + ls0;
        l1 = l1 * cr1 + ls1;

        #pragma unroll
        for (int nt = 0; nt < 8; nt++) {
            oacc[nt][0] *= cr0; oacc[nt][1] *= cr0;
            oacc[nt][2] *= cr1; oacc[nt][3] *= cr1;
        }

        #pragma unroll
        for (int ks = 0; ks < 4; ks++) {
            const unsigned a0 = packh2(sa[2*ks  ][0], sa[2*ks  ][1]);
            const unsigned a1 = packh2(sa[2*ks  ][2], sa[2*ks  ][3]);
            const unsigned a2 = packh2(sa[2*ks+1][0], sa[2*ks+1][1]);
            const unsigned a3 = packh2(sa[2*ks+1][2], sa[2*ks+1][3]);
            #pragma unroll
            for (int dg = 0; dg < 4; dg++) {
                unsigned v0, v1, v2, v3;
                LDSM_X4T(v0, v1, v2, v3, v_frag + bo + (ks * 16 * AP + dg * 16) * 2);
                mma_f16(oacc[2*dg    ], a0, a1, a2, a3, v0, v1);
                mma_f16(oacc[2*dg + 1], a0, a1, a2, a3, v2, v3);
            }
        }

        __syncthreads();
        if (kb + 2 < nkb) issue_tile(kb + 2, buf);
        CP_COMMIT();
    }

    const float inv0 = 1.f / l0;
    const float inv1 = 1.f / l1;
    float* op = O + ((size_t)(b * S_ + row0)) * DM + h * DH;
    #pragma unroll
    for (int nt = 0; nt < 8; nt++) {
        float2 v;
        v.x = oacc[nt][0] * inv0; v.y = oacc[nt][1] * inv0;
        *(float2*)&op[nt * 8 + 2 * t] = v;
        v.x = oacc[nt][2] * inv1; v.y = oacc[nt][3] * inv1;
        *(float2*)&op[(size_t)8 * DM + nt * 8 + 2 * t] = v;
    }
}

// ---------------- residual add + layernorm (fp32 out + fp16 copy) --------
__global__ __launch_bounds__(256)
void ln_kernel(const float* __restrict__ att, const float* __restrict__ resid,
               const float* __restrict__ g, const float* __restrict__ bt,
               float* __restrict__ xout, __half* __restrict__ xh)
{
    const int row = blockIdx.x;
    const int tid = threadIdx.x;

    float4 a = *(const float4*)&att  [(size_t)row * DM + tid * 4];
    float4 r = *(const float4*)&resid[(size_t)row * DM + tid * 4];
    float4 v;
    v.x = a.x + r.x; v.y = a.y + r.y; v.z = a.z + r.z; v.w = a.w + r.w;

    float s1 = v.x + v.y + v.z + v.w;
    float s2 = v.x*v.x + v.y*v.y + v.z*v.z + v.w*v.w;

    __shared__ float sh1[8], sh2[8];
    #pragma unroll
    for (int o = 16; o > 0; o >>= 1) {
        s1 += __shfl_xor_sync(0xffffffffu, s1, o);
        s2 += __shfl_xor_sync(0xffffffffu, s2, o);
    }
    if ((tid & 31) == 0) { sh1[tid >> 5] = s1; sh2[tid >> 5] = s2; }
    __syncthreads();
    float t1 = 0.f, t2 = 0.f;
    #pragma unroll
    for (int i = 0; i < 8; i++) { t1 += sh1[i]; t2 += sh2[i]; }

    const float mu  = t1 * (1.0f / DM);
    const float var = t2 * (1.0f / DM) - mu * mu;
    const float rs  = rsqrtf(var + 1e-5f);

    float4 gg = *(const float4*)&g [tid * 4];
    float4 bb = *(const float4*)&bt[tid * 4];
    float4 o;
    o.x = (v.x - mu) * rs * gg.x + bb.x;
    o.y = (v.y - mu) * rs * gg.y + bb.y;
    o.z = (v.z - mu) * rs * gg.z + bb.z;
    o.w = (v.w - mu) * rs * gg.w + bb.w;
    *(float4*)&xout[(size_t)row * DM + tid * 4] = o;
    uint2 hh;
    hh.x = packh2(o.x, o.y);
    hh.y = packh2(o.z, o.w);
    *(uint2*)&xh[(size_t)row * DM + tid * 4] = hh;
}

// ---------------- launch ---------------------------------------------------
extern "C" void kernel_launch(void* const* d_in, const int* in_sizes, int n_in,
                              void* d_out, int out_size)
{
    const float* q    = (const float*)d_in[0];
    const float* k    = (const float*)d_in[1];
    const float* Wq   = (const float*)d_in[2];
    const float* bq   = (const float*)d_in[3];
    const float* Wk   = (const float*)d_in[4];
    const float* bk   = (const float*)d_in[5];
    const float* Wv   = (const float*)d_in[6];
    const float* bv   = (const float*)d_in[7];
    const float* W1   = (const float*)d_in[8];
    const float* b1   = (const float*)d_in[9];
    const float* W2   = (const float*)d_in[10];
    const float* b2   = (const float*)d_in[11];
    const float* ln_g = (const float*)d_in[12];
    const float* ln_b = (const float*)d_in[13];
    const int*   msk  = (const int*)d_in[14];

    __half *q16, *k16, *wq16, *wk16, *wv16, *w116, *w216, *Qh, *Kh, *Vh, *Xh, *Hh;
    float *Ab, *Xb;
    cudaGetSymbolAddress((void**)&q16,  g_q16);
    cudaGetSymbolAddress((void**)&k16,  g_k16);
    cudaGetSymbolAddress((void**)&wq16, g_wq16);
    cudaGetSymbolAddress((void**)&wk16, g_wk16);
    cudaGetSymbolAddress((void**)&wv16, g_wv16);
    cudaGetSymbolAddress((void**)&w116, g_w116);
    cudaGetSymbolAddress((void**)&w216, g_w216);
    cudaGetSymbolAddress((void**)&Qh,   g_Qh);
    cudaGetSymbolAddress((void**)&Kh,   g_Kh);
    cudaGetSymbolAddress((void**)&Vh,   g_Vh);
    cudaGetSymbolAddress((void**)&Xh,   g_Xh);
    cudaGetSymbolAddress((void**)&Hh,   g_Hh);
    cudaGetSymbolAddress((void**)&Ab,   g_att);
    cudaGetSymbolAddress((void**)&Xb,   g_x);

    cudaFuncSetAttribute(gemm16<1>, cudaFuncAttributeMaxDynamicSharedMemorySize, GSMEM);
    cudaFuncSetAttribute(gemm16<2>, cudaFuncAttributeMaxDynamicSharedMemorySize, GSMEM);
    cudaFuncSetAttribute(gemm_qkv,  cudaFuncAttributeMaxDynamicSharedMemorySize, GSMEM);

    // fused fp32 -> fp16 conversion pass
    f2h_all<<<19456, 256>>>((const float4*)q,  (const float4*)k,
                            (const float4*)Wq, (const float4*)Wk,
                            (const float4*)Wv, (const float4*)W1,
                            (const float4*)W2,
                            (uint2*)q16, (uint2*)k16, (uint2*)wq16,
                            (uint2*)wk16, (uint2*)wv16, (uint2*)w116,
                            (uint2*)w216);

    // merged QKV projections (one launch, grid.z selects which)
    gemm_qkv<<<dim3(DM / 128, MTOK / 128, 3), 256, GSMEM>>>(
        q16, k16, wq16, wk16, wv16, bq, bk, bv, Qh, Kh, Vh);

    // causal attention (fp16 in, fp32 out)
    attn_tc<<<dim3(S_ / 64, H_, B_), 128>>>(Qh, Kh, Vh, Ab, msk);

    // residual + layernorm (fp32 + fp16 outputs)
    ln_kernel<<<MTOK, 256>>>(Ab, q, ln_g, ln_b, Xb, Xh);

    // FFN
    gemm16<1><<<dim3(DFF / 128, MTOK / 128), 256, GSMEM>>>(Xh, w116, b1, Hh, nullptr, MTOK, DFF, DM);
    gemm16<2><<<dim3(DM / 128, MTOK / 128), 256, GSMEM>>>(Hh, w216, b2, d_out, Xb, MTOK, DM, DFF);
}

// round 15
// speedup vs baseline: 1.2397x; 1.0698x over previous
#include <cuda_runtime.h>
#include <cuda_fp16.h>
#include <math.h>
#include <stdint.h>

#define B_    2
#define S_    2048
#define DM    1024
#define H_    16
#define DH    64
#define DFF   4096
#define MTOK  (B_*S_)      // 4096 token rows

// ---------------- scratch (device globals; no allocation) ----------------
__device__ __half g_q16 [MTOK*DM];
__device__ __half g_k16 [MTOK*DM];
__device__ __half g_wq16[DM*DM];
__device__ __half g_wk16[DM*DM];
__device__ __half g_wv16[DM*DM];
__device__ __half g_w116[(size_t)DFF*DM];
__device__ __half g_w216[(size_t)DM*DFF];
__device__ __half g_Qh  [MTOK*DM];
__device__ __half g_Kh  [MTOK*DM];
__device__ __half g_Vh  [MTOK*DM];
__device__ __half g_Xh  [MTOK*DM];
__device__ __half g_Hh  [(size_t)MTOK*DFF];
__device__ float  g_att [MTOK*DM];
__device__ float  g_x   [MTOK*DM];

// ---------------- helpers -------------------------------------------------
__device__ __forceinline__ void mma_f16(float c[4],
                                        unsigned a0, unsigned a1, unsigned a2, unsigned a3,
                                        unsigned b0, unsigned b1) {
    asm volatile("mma.sync.aligned.m16n8k16.row.col.f32.f16.f16.f32 "
                 "{%0,%1,%2,%3}, {%4,%5,%6,%7}, {%8,%9}, {%0,%1,%2,%3};"
                 : "+f"(c[0]), "+f"(c[1]), "+f"(c[2]), "+f"(c[3])
                 : "r"(a0), "r"(a1), "r"(a2), "r"(a3), "r"(b0), "r"(b1));
}

#define LDSM_X4(r0, r1, r2, r3, addr) \
    asm volatile("ldmatrix.sync.aligned.m8n8.x4.shared.b16 {%0,%1,%2,%3}, [%4];" \
                 : "=r"(r0), "=r"(r1), "=r"(r2), "=r"(r3) : "r"(addr))

#define LDSM_X4T(r0, r1, r2, r3, addr) \
    asm volatile("ldmatrix.sync.aligned.m8n8.x4.trans.shared.b16 {%0,%1,%2,%3}, [%4];" \
                 : "=r"(r0), "=r"(r1), "=r"(r2), "=r"(r3) : "r"(addr))

#define CP_ASYNC16(dst, src) \
    asm volatile("cp.async.cg.shared.global [%0], [%1], 16;" :: "r"(dst), "l"(src))
#define CP_COMMIT() asm volatile("cp.async.commit_group;" ::: "memory")
#define CP_WAIT1()  asm volatile("cp.async.wait_group 1;" ::: "memory")

// pack two floats -> f16x2 register (lo = a, hi = b)
__device__ __forceinline__ unsigned packh2(float a, float b) {
    unsigned r;
    asm("cvt.rn.f16x2.f32 %0, %1, %2;" : "=r"(r) : "f"(b), "f"(a));
    return r;
}

// ---------------- fused fp32 -> fp16 conversion (all 7 tensors) ----------
__global__ __launch_bounds__(256)
void f2h_all(const float4* __restrict__ q,  const float4* __restrict__ k,
             const float4* __restrict__ wq, const float4* __restrict__ wk,
             const float4* __restrict__ wv, const float4* __restrict__ w1,
             const float4* __restrict__ w2,
             uint2* __restrict__ q16,  uint2* __restrict__ k16,
             uint2* __restrict__ wq16, uint2* __restrict__ wk16,
             uint2* __restrict__ wv16, uint2* __restrict__ w116,
             uint2* __restrict__ w216)
{
    const int bx = blockIdx.x;
    const float4* src; uint2* dst; int off;
    if      (bx <  4096) { src = q;  dst = q16;  off = bx; }
    else if (bx <  8192) { src = k;  dst = k16;  off = bx - 4096; }
    else if (bx <  9216) { src = wq; dst = wq16; off = bx - 8192; }
    else if (bx < 10240) { src = wk; dst = wk16; off = bx - 9216; }
    else if (bx < 11264) { src = wv; dst = wv16; off = bx - 10240; }
    else if (bx < 15360) { src = w1; dst = w116; off = bx - 11264; }
    else                 { src = w2; dst = w216; off = bx - 15360; }
    const int i = off * 256 + threadIdx.x;
    float4 v = src[i];
    uint2 o;
    o.x = packh2(v.x, v.y);
    o.y = packh2(v.z, v.w);
    dst[i] = o;
}

// ---------------- fp16 GEMM: 128x128 tile, 4 warps 64x64, cp.async 3-stage
#define KC32   32
#define HPW    40                        // pitch 40 halves = 80B = 5*16
#define ABYTES (128 * HPW * 2)           // 10240 B per operand tile
#define STAGEB (2 * ABYTES)              // 20480 B per stage (A + B)
#define NSTG   3
#define GSMEM  (NSTG * STAGEB)           // 61440 B dynamic smem

// mainloop + epilogue body shared by gemm16 and gemm_qkv (128 threads)
template<int EPI>
__device__ __forceinline__
void gemm_body(const __half* __restrict__ A, const __half* __restrict__ Bm,
               const float* __restrict__ bias, void* __restrict__ Cout,
               const float* __restrict__ res, int M, int N, int K,
               int m0, int n0, char* smem)
{
    const uint32_t sbase = (uint32_t)__cvta_generic_to_shared(smem);
    const int tid  = threadIdx.x;
    const int lane = tid & 31;
    const int w    = tid >> 5;           // 0..3
    const int wm   = (w >> 1) * 64;      // 0 or 64
    const int wn   = (w & 1) * 64;       // 0 or 64
    const int g    = lane >> 2;
    const int t    = lane & 3;

    float acc[4][8][4];
    #pragma unroll
    for (int i = 0; i < 4; i++)
        #pragma unroll
        for (int j = 0; j < 8; j++)
            #pragma unroll
            for (int u = 0; u < 4; u++) acc[i][j][u] = 0.f;

    const uint32_t a_frag = sbase + (((uint32_t)(wm + (lane & 15))) * HPW + ((lane >> 4) * 8)) * 2;
    const uint32_t b_frag = sbase + ABYTES + (((uint32_t)(wn + (lane & 7))) * HPW + ((lane >> 3) * 8)) * 2;

    // cp.async staging: 128 threads, 4 slots per operand; slot s = tid + i*128
    // row = s>>2 (0..127 via +i*32), grp = s&3
    const int srow = tid >> 2;           // 0..31
    const int sgrp = tid & 3;
    const uint32_t sdst = sbase + ((uint32_t)(srow * HPW + sgrp * 8)) * 2;
    const __half* gA = A  + (size_t)(m0 + srow) * K + sgrp * 8;
    const __half* gB = Bm + (size_t)(n0 + srow) * K + sgrp * 8;

    auto issue = [&](int c) {
        const uint32_t so = (uint32_t)(c % NSTG) * STAGEB;
        const int k0 = c * KC32;
        #pragma unroll
        for (int i = 0; i < 4; i++) {
            const uint32_t o = so + (uint32_t)(i * 32 * HPW) * 2;
            CP_ASYNC16(sdst + o,          gA + (size_t)(i * 32) * K + k0);
            CP_ASYNC16(sdst + o + ABYTES, gB + (size_t)(i * 32) * K + k0);
        }
    };
    auto compute = [&](int st) {
        const uint32_t bo = (uint32_t)st * STAGEB;
        unsigned bq[8][4];
        #pragma unroll
        for (int nt = 0; nt < 8; nt++)
            LDSM_X4(bq[nt][0], bq[nt][1], bq[nt][2], bq[nt][3],
                    b_frag + bo + nt * (8 * HPW * 2));
        #pragma unroll
        for (int kh = 0; kh < 2; kh++) {
            unsigned aq[4][4];
            #pragma unroll
            for (int mt = 0; mt < 4; mt++)
                LDSM_X4(aq[mt][0], aq[mt][1], aq[mt][2], aq[mt][3],
                        a_frag + bo + mt * (16 * HPW * 2) + kh * 32);
            #pragma unroll
            for (int mt = 0; mt < 4; mt++)
                #pragma unroll
                for (int nt = 0; nt < 8; nt++)
                    mma_f16(acc[mt][nt], aq[mt][0], aq[mt][1], aq[mt][2], aq[mt][3],
                            bq[nt][kh * 2], bq[nt][kh * 2 + 1]);
        }
    };

    const int NC = K / KC32;
    issue(0); CP_COMMIT();
    if (NC > 1) issue(1);
    CP_COMMIT();
    for (int c = 0; c < NC; c++) {
        CP_WAIT1();
        __syncthreads();
        if (c + 2 < NC) issue(c + 2);
        CP_COMMIT();
        compute(c % NSTG);
    }

    // epilogue: warp covers 64x64
    #pragma unroll
    for (int mt = 0; mt < 4; mt++) {
        #pragma unroll
        for (int half = 0; half < 2; half++) {
            const int row = m0 + wm + mt * 16 + g + half * 8;
            #pragma unroll
            for (int nt = 0; nt < 8; nt++) {
                const int col = n0 + wn + nt * 8 + 2 * t;
                float v0 = acc[mt][nt][half * 2 + 0] + bias[col];
                float v1 = acc[mt][nt][half * 2 + 1] + bias[col + 1];
                if (EPI == 1) {
                    v0 = 0.5f * v0 * (1.0f + erff(v0 * 0.70710678118654752f));
                    v1 = 0.5f * v1 * (1.0f + erff(v1 * 0.70710678118654752f));
                }
                if (EPI == 2) {
                    v0 += res[(size_t)row * N + col];
                    v1 += res[(size_t)row * N + col + 1];
                    float2 o; o.x = v0; o.y = v1;
                    *(float2*)&((float*)Cout)[(size_t)row * N + col] = o;
                } else {
                    *(unsigned*)&((__half*)Cout)[(size_t)row * N + col] = packh2(v0, v1);
                }
            }
        }
    }
}

template<int EPI>
__global__ __launch_bounds__(128, 2)
void gemm16(const __half* __restrict__ A, const __half* __restrict__ Bm,
            const float* __restrict__ bias, void* __restrict__ Cout,
            const float* __restrict__ res, int M, int N, int K)
{
    extern __shared__ char smem[];
    gemm_body<EPI>(A, Bm, bias, Cout, res, M, N, K,
                   blockIdx.y * 128, blockIdx.x * 128, smem);
}

// merged QKV projection: grid.z selects {q16*Wq->Qh, k16*Wk->Kh, k16*Wv->Vh}
__global__ __launch_bounds__(128, 2)
void gemm_qkv(const __half* __restrict__ q16, const __half* __restrict__ k16,
              const __half* __restrict__ wq,  const __half* __restrict__ wk,
              const __half* __restrict__ wv,
              const float* __restrict__ bq,   const float* __restrict__ bk,
              const float* __restrict__ bv,
              __half* __restrict__ Qh, __half* __restrict__ Kh,
              __half* __restrict__ Vh)
{
    extern __shared__ char smem[];
    const int z = blockIdx.z;
    const __half* A  = (z == 0) ? q16 : k16;
    const __half* Bm = (z == 0) ? wq : (z == 1 ? wk : wv);
    const float*  bs = (z == 0) ? bq : (z == 1 ? bk : bv);
    __half*       C  = (z == 0) ? Qh : (z == 1 ? Kh : Vh);
    gemm_body<0>(A, Bm, bs, C, nullptr, MTOK, DM, DM,
                 blockIdx.y * 128, blockIdx.x * 128, smem);
}

// ---------------- fp16 tensor-core causal flash attention (R11/R12) ------
#define AP 72
#define ATILE (64 * AP)   // halves per tile

__global__ __launch_bounds__(128, 3)
void attn_tc(const __half* __restrict__ Q, const __half* __restrict__ K,
             const __half* __restrict__ V, float* __restrict__ O,
             const int* __restrict__ use_mask)
{
    __shared__ __half Ks[2][ATILE];
    __shared__ __half Vs[2][ATILE];

    const int tid  = threadIdx.x;
    const int lane = tid & 31;
    const int w    = tid >> 5;
    const int g    = lane >> 2;
    const int t    = lane & 3;
    const int qb   = (gridDim.x - 1) - blockIdx.x;
    const int h    = blockIdx.y;
    const int b    = blockIdx.z;
    const int q0   = qb * 64;
    const int causal = use_mask[0];
    const int row0 = q0 + w * 16 + g;

    unsigned qf[4][4];
    {
        const __half* qp  = Q + ((size_t)(b * S_ + row0)) * DM + h * DH;
        const __half* qp8 = qp + 8 * DM;
        #pragma unroll
        for (int ks = 0; ks < 4; ks++) {
            const int c = ks * 16 + 2 * t;
            qf[ks][0] = *(const unsigned*)&qp [c];
            qf[ks][1] = *(const unsigned*)&qp8[c];
            qf[ks][2] = *(const unsigned*)&qp [c + 8];
            qf[ks][3] = *(const unsigned*)&qp8[c + 8];
        }
    }

    const uint32_t sK = (uint32_t)__cvta_generic_to_shared(&Ks[0][0]);
    const uint32_t sV = (uint32_t)__cvta_generic_to_shared(&Vs[0][0]);
    const uint32_t k_frag = sK + (((uint32_t)(lane & 7))  * AP + ((lane >> 3) * 8)) * 2;
    const uint32_t v_frag = sV + (((uint32_t)(lane & 15)) * AP + ((lane >> 4) * 8)) * 2;

    const int sr = tid >> 3;
    const int sg = tid & 7;
    const uint32_t kdst = sK + ((uint32_t)(sr * AP + sg * 8)) * 2;
    const uint32_t vdst = sV + ((uint32_t)(sr * AP + sg * 8)) * 2;
    const __half* ksrc = K + ((size_t)(b * S_) + sr) * DM + h * DH + sg * 8;
    const __half* vsrc = V + ((size_t)(b * S_) + sr) * DM + h * DH + sg * 8;

    auto issue_tile = [&](int kb, int buf) {
        const uint32_t bo = (uint32_t)buf * (ATILE * 2);
        const size_t go = (size_t)(kb * 64) * DM;
        #pragma unroll
        for (int i = 0; i < 4; i++) {
            const uint32_t so = (uint32_t)(i * 16 * AP) * 2;
            const size_t gg = go + (size_t)(i * 16) * DM;
            CP_ASYNC16(kdst + bo + so, ksrc + gg);
            CP_ASYNC16(vdst + bo + so, vsrc + gg);
        }
    };

    float m0 = -INFINITY, m1 = -INFINITY, l0 = 0.f, l1 = 0.f;
    float oacc[8][4];
    #pragma unroll
    for (int nt = 0; nt < 8; nt++)
        #pragma unroll
        for (int u = 0; u < 4; u++) oacc[nt][u] = 0.f;

    const int nkb = causal ? (qb + 1) : (S_ / 64);

    issue_tile(0, 0);
    CP_COMMIT();
    if (nkb > 1) issue_tile(1, 1);
    CP_COMMIT();

    for (int kb = 0; kb < nkb; kb++) {
        const int buf = kb & 1;
        CP_WAIT1();
        __syncthreads();

        const uint32_t bo = (uint32_t)buf * (ATILE * 2);

        float sa[8][4];
        #pragma unroll
        for (int nt = 0; nt < 8; nt++)
            #pragma unroll
            for (int u = 0; u < 4; u++) sa[nt][u] = 0.f;

        #pragma unroll
        for (int nt = 0; nt < 8; nt++) {
            unsigned kq[8];
            LDSM_X4(kq[0], kq[1], kq[2], kq[3], k_frag + bo + (nt * 8 * AP) * 2);
            LDSM_X4(kq[4], kq[5], kq[6], kq[7], k_frag + bo + (nt * 8 * AP) * 2 + 64);
            #pragma unroll
            for (int ks = 0; ks < 4; ks++)
                mma_f16(sa[nt], qf[ks][0], qf[ks][1], qf[ks][2], qf[ks][3],
                        kq[ks * 2], kq[ks * 2 + 1]);
        }

        const bool mask_tile = causal && (kb == qb);
        float smax0 = -INFINITY, smax1 = -INFINITY;
        #pragma unroll
        for (int nt = 0; nt < 8; nt++) {
            const int col = kb * 64 + nt * 8 + 2 * t;
            sa[nt][0] *= 0.125f; sa[nt][1] *= 0.125f;
            sa[nt][2] *= 0.125f; sa[nt][3] *= 0.125f;
            if (mask_tile) {
                if (col     > row0)     sa[nt][0] = -1e9f;
                if (col + 1 > row0)     sa[nt][1] = -1e9f;
                if (col     > row0 + 8) sa[nt][2] = -1e9f;
                if (col + 1 > row0 + 8) sa[nt][3] = -1e9f;
            }
            smax0 = fmaxf(smax0, fmaxf(sa[nt][0], sa[nt][1]));
            smax1 = fmaxf(smax1, fmaxf(sa[nt][2], sa[nt][3]));
        }
        smax0 = fmaxf(smax0, __shfl_xor_sync(0xffffffffu, smax0, 1));
        smax0 = fmaxf(smax0, __shfl_xor_sync(0xffffffffu, smax0, 2));
        smax1 = fmaxf(smax1, __shfl_xor_sync(0xffffffffu, smax1, 1));
        smax1 = fmaxf(smax1, __shfl_xor_sync(0xffffffffu, smax1, 2));

        const float m0n = fmaxf(m0, smax0);
        const float m1n = fmaxf(m1, smax1);
        const float cr0 = __expf(m0 - m0n);
        const float cr1 = __expf(m1 - m1n);
        m0 = m0n; m1 = m1n;

        float ls0 = 0.f, ls1 = 0.f;
        #pragma unroll
        for (int nt = 0; nt < 8; nt++) {
            sa[nt][0] = __expf(sa[nt][0] - m0n);
            sa[nt][1] = __expf(sa[nt][1] - m0n);
            sa[nt][2] = __expf(sa[nt][2] - m1n);
            sa[nt][3] = __expf(sa[nt][3] - m1n);
            ls0 += sa[nt][0] + sa[nt][1];
            ls1 += sa[nt][2] + sa[nt][3];
        }
        ls0 += __shfl_xor_sync(0xffffffffu, ls0, 1);
        ls0 += __shfl_xor_sync(0xffffffffu, ls0, 2);
        ls1 += __shfl_xor_sync(0xffffffffu, ls1, 1);
        ls1 += __shfl_xor_sync(0xffffffffu, ls1, 2);
        l0 = l0 * cr0 + ls0;
        l1 = l1 * cr1 + ls1;

        #pragma unroll
        for (int nt = 0; nt < 8; nt++) {
            oacc[nt][0] *= cr0; oacc[nt][1] *= cr0;
            oacc[nt][2] *= cr1; oacc[nt][3] *= cr1;
        }

        #pragma unroll
        for (int ks = 0; ks < 4; ks++) {
            const unsigned a0 = packh2(sa[2*ks  ][0], sa[2*ks  ][1]);
            const unsigned a1 = packh2(sa[2*ks  ][2], sa[2*ks  ][3]);
            const unsigned a2 = packh2(sa[2*ks+1][0], sa[2*ks+1][1]);
            const unsigned a3 = packh2(sa[2*ks+1][2], sa[2*ks+1][3]);
            #pragma unroll
            for (int dg = 0; dg < 4; dg++) {
                unsigned v0, v1, v2, v3;
                LDSM_X4T(v0, v1, v2, v3, v_frag + bo + (ks * 16 * AP + dg * 16) * 2);
                mma_f16(oacc[2*dg    ], a0, a1, a2, a3, v0, v1);
                mma_f16(oacc[2*dg + 1], a0, a1, a2, a3, v2, v3);
            }
        }

        __syncthreads();
        if (kb + 2 < nkb) issue_tile(kb + 2, buf);
        CP_COMMIT();
    }

    const float inv0 = 1.f / l0;
    const float inv1 = 1.f / l1;
    float* op = O + ((size_t)(b * S_ + row0)) * DM + h * DH;
    #pragma unroll
    for (int nt = 0; nt < 8; nt++) {
        float2 v;
        v.x = oacc[nt][0] * inv0; v.y = oacc[nt][1] * inv0;
        *(float2*)&op[nt * 8 + 2 * t] = v;
        v.x = oacc[nt][2] * inv1; v.y = oacc[nt][3] * inv1;
        *(float2*)&op[(size_t)8 * DM + nt * 8 + 2 * t] = v;
    }
}

// ---------------- residual add + layernorm (fp32 out + fp16 copy) --------
__global__ __launch_bounds__(256)
void ln_kernel(const float* __restrict__ att, const float* __restrict__ resid,
               const float* __restrict__ g, const float* __restrict__ bt,
               float* __restrict__ xout, __half* __restrict__ xh)
{
    const int row = blockIdx.x;
    const int tid = threadIdx.x;

    float4 a = *(const float4*)&att  [(size_t)row * DM + tid * 4];
    float4 r = *(const float4*)&resid[(size_t)row * DM + tid * 4];
    float4 v;
    v.x = a.x + r.x; v.y = a.y + r.y; v.z = a.z + r.z; v.w = a.w + r.w;

    float s1 = v.x + v.y + v.z + v.w;
    float s2 = v.x*v.x + v.y*v.y + v.z*v.z + v.w*v.w;

    __shared__ float sh1[8], sh2[8];
    #pragma unroll
    for (int o = 16; o > 0; o >>= 1) {
        s1 += __shfl_xor_sync(0xffffffffu, s1, o);
        s2 += __shfl_xor_sync(0xffffffffu, s2, o);
    }
    if ((tid & 31) == 0) { sh1[tid >> 5] = s1; sh2[tid >> 5] = s2; }
    __syncthreads();
    float t1 = 0.f, t2 = 0.f;
    #pragma unroll
    for (int i = 0; i < 8; i++) { t1 += sh1[i]; t2 += sh2[i]; }

    const float mu  = t1 * (1.0f / DM);
    const float var = t2 * (1.0f / DM) - mu * mu;
    const float rs  = rsqrtf(var + 1e-5f);

    float4 gg = *(const float4*)&g [tid * 4];
    float4 bb = *(const float4*)&bt[tid * 4];
    float4 o;
    o.x = (v.x - mu) * rs * gg.x + bb.x;
    o.y = (v.y - mu) * rs * gg.y + bb.y;
    o.z = (v.z - mu) * rs * gg.z + bb.z;
    o.w = (v.w - mu) * rs * gg.w + bb.w;
    *(float4*)&xout[(size_t)row * DM + tid * 4] = o;
    uint2 hh;
    hh.x = packh2(o.x, o.y);
    hh.y = packh2(o.z, o.w);
    *(uint2*)&xh[(size_t)row * DM + tid * 4] = hh;
}

// ---------------- launch ---------------------------------------------------
extern "C" void kernel_launch(void* const* d_in, const int* in_sizes, int n_in,
                              void* d_out, int out_size)
{
    const float* q    = (const float*)d_in[0];
    const float* k    = (const float*)d_in[1];
    const float* Wq   = (const float*)d_in[2];
    const float* bq   = (const float*)d_in[3];
    const float* Wk   = (const float*)d_in[4];
    const float* bk   = (const float*)d_in[5];
    const float* Wv   = (const float*)d_in[6];
    const float* bv   = (const float*)d_in[7];
    const float* W1   = (const float*)d_in[8];
    const float* b1   = (const float*)d_in[9];
    const float* W2   = (const float*)d_in[10];
    const float* b2   = (const float*)d_in[11];
    const float* ln_g = (const float*)d_in[12];
    const float* ln_b = (const float*)d_in[13];
    const int*   msk  = (const int*)d_in[14];

    __half *q16, *k16, *wq16, *wk16, *wv16, *w116, *w216, *Qh, *Kh, *Vh, *Xh, *Hh;
    float *Ab, *Xb;
    cudaGetSymbolAddress((void**)&q16,  g_q16);
    cudaGetSymbolAddress((void**)&k16,  g_k16);
    cudaGetSymbolAddress((void**)&wq16, g_wq16);
    cudaGetSymbolAddress((void**)&wk16, g_wk16);
    cudaGetSymbolAddress((void**)&wv16, g_wv16);
    cudaGetSymbolAddress((void**)&w116, g_w116);
    cudaGetSymbolAddress((void**)&w216, g_w216);
    cudaGetSymbolAddress((void**)&Qh,   g_Qh);
    cudaGetSymbolAddress((void**)&Kh,   g_Kh);
    cudaGetSymbolAddress((void**)&Vh,   g_Vh);
    cudaGetSymbolAddress((void**)&Xh,   g_Xh);
    cudaGetSymbolAddress((void**)&Hh,   g_Hh);
    cudaGetSymbolAddress((void**)&Ab,   g_att);
    cudaGetSymbolAddress((void**)&Xb,   g_x);

    cudaFuncSetAttribute(gemm16<1>, cudaFuncAttributeMaxDynamicSharedMemorySize, GSMEM);
    cudaFuncSetAttribute(gemm16<2>, cudaFuncAttributeMaxDynamicSharedMemorySize, GSMEM);
    cudaFuncSetAttribute(gemm_qkv,  cudaFuncAttributeMaxDynamicSharedMemorySize, GSMEM);

    // fused fp32 -> fp16 conversion pass
    f2h_all<<<19456, 256>>>((const float4*)q,  (const float4*)k,
                            (const float4*)Wq, (const float4*)Wk,
                            (const float4*)Wv, (const float4*)W1,
                            (const float4*)W2,
                            (uint2*)q16, (uint2*)k16, (uint2*)wq16,
                            (uint2*)wk16, (uint2*)wv16, (uint2*)w116,
                            (uint2*)w216);

    // merged QKV projections (one launch, grid.z selects which)
    gemm_qkv<<<dim3(DM / 128, MTOK / 128, 3), 128, GSMEM>>>(
        q16, k16, wq16, wk16, wv16, bq, bk, bv, Qh, Kh, Vh);

    // causal attention (fp16 in, fp32 out)
    attn_tc<<<dim3(S_ / 64, H_, B_), 128>>>(Qh, Kh, Vh, Ab, msk);

    // residual + layernorm (fp32 + fp16 outputs)
    ln_kernel<<<MTOK, 256>>>(Ab, q, ln_g, ln_b, Xb, Xh);

    // FFN
    gemm16<1><<<dim3(DFF / 128, MTOK / 128), 128, GSMEM>>>(Xh, w116, b1, Hh, nullptr, MTOK, DFF, DM);
    gemm16<2><<<dim3(DM / 128, MTOK / 128), 128, GSMEM>>>(Hh, w216, b2, d_out, Xb, MTOK, DM, DFF);
}

// round 16
// speedup vs baseline: 1.2511x; 1.0092x over previous
#include <cuda_runtime.h>
#include <cuda_fp16.h>
#include <math.h>
#include <stdint.h>

#define B_    2
#define S_    2048
#define DM    1024
#define H_    16
#define DH    64
#define DFF   4096
#define MTOK  (B_*S_)      // 4096 token rows

// ---------------- scratch (device globals; no allocation) ----------------
__device__ __half g_q16 [MTOK*DM];
__device__ __half g_k16 [MTOK*DM];
__device__ __half g_wq16[DM*DM];
__device__ __half g_wk16[DM*DM];
__device__ __half g_wv16[DM*DM];
__device__ __half g_w116[(size_t)DFF*DM];
__device__ __half g_w216[(size_t)DM*DFF];
__device__ __half g_Qh  [MTOK*DM];
__device__ __half g_Kh  [MTOK*DM];
__device__ __half g_Vh  [MTOK*DM];
__device__ __half g_Xh  [MTOK*DM];
__device__ __half g_Hh  [(size_t)MTOK*DFF];
__device__ float  g_att [MTOK*DM];
__device__ float  g_x   [MTOK*DM];

// ---------------- helpers -------------------------------------------------
__device__ __forceinline__ void mma_f16(float c[4],
                                        unsigned a0, unsigned a1, unsigned a2, unsigned a3,
                                        unsigned b0, unsigned b1) {
    asm volatile("mma.sync.aligned.m16n8k16.row.col.f32.f16.f16.f32 "
                 "{%0,%1,%2,%3}, {%4,%5,%6,%7}, {%8,%9}, {%0,%1,%2,%3};"
                 : "+f"(c[0]), "+f"(c[1]), "+f"(c[2]), "+f"(c[3])
                 : "r"(a0), "r"(a1), "r"(a2), "r"(a3), "r"(b0), "r"(b1));
}

#define LDSM_X4(r0, r1, r2, r3, addr) \
    asm volatile("ldmatrix.sync.aligned.m8n8.x4.shared.b16 {%0,%1,%2,%3}, [%4];" \
                 : "=r"(r0), "=r"(r1), "=r"(r2), "=r"(r3) : "r"(addr))

#define LDSM_X4T(r0, r1, r2, r3, addr) \
    asm volatile("ldmatrix.sync.aligned.m8n8.x4.trans.shared.b16 {%0,%1,%2,%3}, [%4];" \
                 : "=r"(r0), "=r"(r1), "=r"(r2), "=r"(r3) : "r"(addr))

#define CP_ASYNC16(dst, src) \
    asm volatile("cp.async.cg.shared.global [%0], [%1], 16;" :: "r"(dst), "l"(src))
#define CP_COMMIT() asm volatile("cp.async.commit_group;" ::: "memory")
#define CP_WAIT1()  asm volatile("cp.async.wait_group 1;" ::: "memory")

// pack two floats -> f16x2 register (lo = a, hi = b)
__device__ __forceinline__ unsigned packh2(float a, float b) {
    unsigned r;
    asm("cvt.rn.f16x2.f32 %0, %1, %2;" : "=r"(r) : "f"(b), "f"(a));
    return r;
}

// exact scale of packed f16x2 by power of two (0.125): exponent shift, no rounding
__device__ __forceinline__ unsigned hscale8(unsigned x) {
    __half2 v = *(__half2*)&x;
    v = __hmul2(v, __half2half2(__float2half(0.125f)));
    return *(unsigned*)&v;
}

// ---------------- fused fp32 -> fp16 conversion (all 7 tensors) ----------
__global__ __launch_bounds__(256)
void f2h_all(const float4* __restrict__ q,  const float4* __restrict__ k,
             const float4* __restrict__ wq, const float4* __restrict__ wk,
             const float4* __restrict__ wv, const float4* __restrict__ w1,
             const float4* __restrict__ w2,
             uint2* __restrict__ q16,  uint2* __restrict__ k16,
             uint2* __restrict__ wq16, uint2* __restrict__ wk16,
             uint2* __restrict__ wv16, uint2* __restrict__ w116,
             uint2* __restrict__ w216)
{
    const int bx = blockIdx.x;
    const float4* src; uint2* dst; int off;
    if      (bx <  4096) { src = q;  dst = q16;  off = bx; }
    else if (bx <  8192) { src = k;  dst = k16;  off = bx - 4096; }
    else if (bx <  9216) { src = wq; dst = wq16; off = bx - 8192; }
    else if (bx < 10240) { src = wk; dst = wk16; off = bx - 9216; }
    else if (bx < 11264) { src = wv; dst = wv16; off = bx - 10240; }
    else if (bx < 15360) { src = w1; dst = w116; off = bx - 11264; }
    else                 { src = w2; dst = w216; off = bx - 15360; }
    const int i = off * 256 + threadIdx.x;
    float4 v = src[i];
    uint2 o;
    o.x = packh2(v.x, v.y);
    o.y = packh2(v.z, v.w);
    dst[i] = o;
}

// ---------------- fp16 GEMM: 128x128 tile, 4 warps 64x64, cp.async 3-stage
#define KC32   32
#define HPW    40                        // pitch 40 halves = 80B = 5*16
#define ABYTES (128 * HPW * 2)           // 10240 B per operand tile
#define STAGEB (2 * ABYTES)              // 20480 B per stage (A + B)
#define NSTG   3
#define GSMEM  (NSTG * STAGEB)           // 61440 B dynamic smem

// mainloop + epilogue body shared by gemm16 and gemm_qkv (128 threads)
template<int EPI>
__device__ __forceinline__
void gemm_body(const __half* __restrict__ A, const __half* __restrict__ Bm,
               const float* __restrict__ bias, void* __restrict__ Cout,
               const float* __restrict__ res, int M, int N, int K,
               int m0, int n0, char* smem)
{
    const uint32_t sbase = (uint32_t)__cvta_generic_to_shared(smem);
    const int tid  = threadIdx.x;
    const int lane = tid & 31;
    const int w    = tid >> 5;           // 0..3
    const int wm   = (w >> 1) * 64;      // 0 or 64
    const int wn   = (w & 1) * 64;       // 0 or 64
    const int g    = lane >> 2;
    const int t    = lane & 3;

    float acc[4][8][4];
    #pragma unroll
    for (int i = 0; i < 4; i++)
        #pragma unroll
        for (int j = 0; j < 8; j++)
            #pragma unroll
            for (int u = 0; u < 4; u++) acc[i][j][u] = 0.f;

    const uint32_t a_frag = sbase + (((uint32_t)(wm + (lane & 15))) * HPW + ((lane >> 4) * 8)) * 2;
    const uint32_t b_frag = sbase + ABYTES + (((uint32_t)(wn + (lane & 7))) * HPW + ((lane >> 3) * 8)) * 2;

    const int srow = tid >> 2;           // 0..31
    const int sgrp = tid & 3;
    const uint32_t sdst = sbase + ((uint32_t)(srow * HPW + sgrp * 8)) * 2;
    const __half* gA = A  + (size_t)(m0 + srow) * K + sgrp * 8;
    const __half* gB = Bm + (size_t)(n0 + srow) * K + sgrp * 8;

    auto issue = [&](int c) {
        const uint32_t so = (uint32_t)(c % NSTG) * STAGEB;
        const int k0 = c * KC32;
        #pragma unroll
        for (int i = 0; i < 4; i++) {
            const uint32_t o = so + (uint32_t)(i * 32 * HPW) * 2;
            CP_ASYNC16(sdst + o,          gA + (size_t)(i * 32) * K + k0);
            CP_ASYNC16(sdst + o + ABYTES, gB + (size_t)(i * 32) * K + k0);
        }
    };
    auto compute = [&](int st) {
        const uint32_t bo = (uint32_t)st * STAGEB;
        unsigned bq[8][4];
        #pragma unroll
        for (int nt = 0; nt < 8; nt++)
            LDSM_X4(bq[nt][0], bq[nt][1], bq[nt][2], bq[nt][3],
                    b_frag + bo + nt * (8 * HPW * 2));
        #pragma unroll
        for (int kh = 0; kh < 2; kh++) {
            unsigned aq[4][4];
            #pragma unroll
            for (int mt = 0; mt < 4; mt++)
                LDSM_X4(aq[mt][0], aq[mt][1], aq[mt][2], aq[mt][3],
                        a_frag + bo + mt * (16 * HPW * 2) + kh * 32);
            #pragma unroll
            for (int mt = 0; mt < 4; mt++)
                #pragma unroll
                for (int nt = 0; nt < 8; nt++)
                    mma_f16(acc[mt][nt], aq[mt][0], aq[mt][1], aq[mt][2], aq[mt][3],
                            bq[nt][kh * 2], bq[nt][kh * 2 + 1]);
        }
    };

    const int NC = K / KC32;
    issue(0); CP_COMMIT();
    if (NC > 1) issue(1);
    CP_COMMIT();
    for (int c = 0; c < NC; c++) {
        CP_WAIT1();
        __syncthreads();
        if (c + 2 < NC) issue(c + 2);
        CP_COMMIT();
        compute(c % NSTG);
    }

    #pragma unroll
    for (int mt = 0; mt < 4; mt++) {
        #pragma unroll
        for (int half = 0; half < 2; half++) {
            const int row = m0 + wm + mt * 16 + g + half * 8;
            #pragma unroll
            for (int nt = 0; nt < 8; nt++) {
                const int col = n0 + wn + nt * 8 + 2 * t;
                float v0 = acc[mt][nt][half * 2 + 0] + bias[col];
                float v1 = acc[mt][nt][half * 2 + 1] + bias[col + 1];
                if (EPI == 1) {
                    v0 = 0.5f * v0 * (1.0f + erff(v0 * 0.70710678118654752f));
                    v1 = 0.5f * v1 * (1.0f + erff(v1 * 0.70710678118654752f));
                }
                if (EPI == 2) {
                    v0 += res[(size_t)row * N + col];
                    v1 += res[(size_t)row * N + col + 1];
                    float2 o; o.x = v0; o.y = v1;
                    *(float2*)&((float*)Cout)[(size_t)row * N + col] = o;
                } else {
                    *(unsigned*)&((__half*)Cout)[(size_t)row * N + col] = packh2(v0, v1);
                }
            }
        }
    }
}

template<int EPI>
__global__ __launch_bounds__(128, 2)
void gemm16(const __half* __restrict__ A, const __half* __restrict__ Bm,
            const float* __restrict__ bias, void* __restrict__ Cout,
            const float* __restrict__ res, int M, int N, int K)
{
    extern __shared__ char smem[];
    gemm_body<EPI>(A, Bm, bias, Cout, res, M, N, K,
                   blockIdx.y * 128, blockIdx.x * 128, smem);
}

// merged QKV projection: grid.z selects {q16*Wq->Qh, k16*Wk->Kh, k16*Wv->Vh}
__global__ __launch_bounds__(128, 2)
void gemm_qkv(const __half* __restrict__ q16, const __half* __restrict__ k16,
              const __half* __restrict__ wq,  const __half* __restrict__ wk,
              const __half* __restrict__ wv,
              const float* __restrict__ bq,   const float* __restrict__ bk,
              const float* __restrict__ bv,
              __half* __restrict__ Qh, __half* __restrict__ Kh,
              __half* __restrict__ Vh)
{
    extern __shared__ char smem[];
    const int z = blockIdx.z;
    const __half* A  = (z == 0) ? q16 : k16;
    const __half* Bm = (z == 0) ? wq : (z == 1 ? wk : wv);
    const float*  bs = (z == 0) ? bq : (z == 1 ? bk : bv);
    __half*       C  = (z == 0) ? Qh : (z == 1 ? Kh : Vh);
    gemm_body<0>(A, Bm, bs, C, nullptr, MTOK, DM, DM,
                 blockIdx.y * 128, blockIdx.x * 128, smem);
}

// ---------------- fp16 tensor-core causal flash attention ----------------
// 64 q rows/CTA, 4 warps, cp.async double-buffered kv; 4 CTAs/SM target.
#define AP 72
#define ATILE (64 * AP)   // halves per tile

__global__ __launch_bounds__(128, 4)
void attn_tc(const __half* __restrict__ Q, const __half* __restrict__ K,
             const __half* __restrict__ V, float* __restrict__ O,
             const int* __restrict__ use_mask)
{
    __shared__ __half Ks[2][ATILE];
    __shared__ __half Vs[2][ATILE];

    const int tid  = threadIdx.x;
    const int lane = tid & 31;
    const int w    = tid >> 5;
    const int g    = lane >> 2;
    const int t    = lane & 3;
    const int qb   = (gridDim.x - 1) - blockIdx.x;
    const int h    = blockIdx.y;
    const int b    = blockIdx.z;
    const int q0   = qb * 64;
    const int causal = use_mask[0];
    const int row0 = q0 + w * 16 + g;

    // Q fragments, pre-scaled by 1/8 (exact: power-of-two exponent shift)
    unsigned qf[4][4];
    {
        const __half* qp  = Q + ((size_t)(b * S_ + row0)) * DM + h * DH;
        const __half* qp8 = qp + 8 * DM;
        #pragma unroll
        for (int ks = 0; ks < 4; ks++) {
            const int c = ks * 16 + 2 * t;
            qf[ks][0] = hscale8(*(const unsigned*)&qp [c]);
            qf[ks][1] = hscale8(*(const unsigned*)&qp8[c]);
            qf[ks][2] = hscale8(*(const unsigned*)&qp [c + 8]);
            qf[ks][3] = hscale8(*(const unsigned*)&qp8[c + 8]);
        }
    }

    const uint32_t sK = (uint32_t)__cvta_generic_to_shared(&Ks[0][0]);
    const uint32_t sV = (uint32_t)__cvta_generic_to_shared(&Vs[0][0]);
    const uint32_t k_frag = sK + (((uint32_t)(lane & 7))  * AP + ((lane >> 3) * 8)) * 2;
    const uint32_t v_frag = sV + (((uint32_t)(lane & 15)) * AP + ((lane >> 4) * 8)) * 2;

    const int sr = tid >> 3;
    const int sg = tid & 7;
    const uint32_t kdst = sK + ((uint32_t)(sr * AP + sg * 8)) * 2;
    const uint32_t vdst = sV + ((uint32_t)(sr * AP + sg * 8)) * 2;
    const __half* ksrc = K + ((size_t)(b * S_) + sr) * DM + h * DH + sg * 8;
    const __half* vsrc = V + ((size_t)(b * S_) + sr) * DM + h * DH + sg * 8;

    auto issue_tile = [&](int kb, int buf) {
        const uint32_t bo = (uint32_t)buf * (ATILE * 2);
        const size_t go = (size_t)(kb * 64) * DM;
        #pragma unroll
        for (int i = 0; i < 4; i++) {
            const uint32_t so = (uint32_t)(i * 16 * AP) * 2;
            const size_t gg = go + (size_t)(i * 16) * DM;
            CP_ASYNC16(kdst + bo + so, ksrc + gg);
            CP_ASYNC16(vdst + bo + so, vsrc + gg);
        }
    };

    float m0 = -INFINITY, m1 = -INFINITY, l0 = 0.f, l1 = 0.f;
    float oacc[8][4];
    #pragma unroll
    for (int nt = 0; nt < 8; nt++)
        #pragma unroll
        for (int u = 0; u < 4; u++) oacc[nt][u] = 0.f;

    const int nkb = causal ? (qb + 1) : (S_ / 64);

    issue_tile(0, 0);
    CP_COMMIT();
    if (nkb > 1) issue_tile(1, 1);
    CP_COMMIT();

    for (int kb = 0; kb < nkb; kb++) {
        const int buf = kb & 1;
        CP_WAIT1();
        __syncthreads();

        const uint32_t bo = (uint32_t)buf * (ATILE * 2);

        float sa[8][4];
        #pragma unroll
        for (int nt = 0; nt < 8; nt++)
            #pragma unroll
            for (int u = 0; u < 4; u++) sa[nt][u] = 0.f;

        #pragma unroll
        for (int nt = 0; nt < 8; nt++) {
            unsigned kq[8];
            LDSM_X4(kq[0], kq[1], kq[2], kq[3], k_frag + bo + (nt * 8 * AP) * 2);
            LDSM_X4(kq[4], kq[5], kq[6], kq[7], k_frag + bo + (nt * 8 * AP) * 2 + 64);
            #pragma unroll
            for (int ks = 0; ks < 4; ks++)
                mma_f16(sa[nt], qf[ks][0], qf[ks][1], qf[ks][2], qf[ks][3],
                        kq[ks * 2], kq[ks * 2 + 1]);
        }

        const bool mask_tile = causal && (kb == qb);
        float smax0 = -INFINITY, smax1 = -INFINITY;
        #pragma unroll
        for (int nt = 0; nt < 8; nt++) {
            const int col = kb * 64 + nt * 8 + 2 * t;
            if (mask_tile) {
                if (col     > row0)     sa[nt][0] = -1e9f;
                if (col + 1 > row0)     sa[nt][1] = -1e9f;
                if (col     > row0 + 8) sa[nt][2] = -1e9f;
                if (col + 1 > row0 + 8) sa[nt][3] = -1e9f;
            }
            smax0 = fmaxf(smax0, fmaxf(sa[nt][0], sa[nt][1]));
            smax1 = fmaxf(smax1, fmaxf(sa[nt][2], sa[nt][3]));
        }
        smax0 = fmaxf(smax0, __shfl_xor_sync(0xffffffffu, smax0, 1));
        smax0 = fmaxf(smax0, __shfl_xor_sync(0xffffffffu, smax0, 2));
        smax1 = fmaxf(smax1, __shfl_xor_sync(0xffffffffu, smax1, 1));
        smax1 = fmaxf(smax1, __shfl_xor_sync(0xffffffffu, smax1, 2));

        const float m0n = fmaxf(m0, smax0);
        const float m1n = fmaxf(m1, smax1);
        const float cr0 = __expf(m0 - m0n);
        const float cr1 = __expf(m1 - m1n);
        m0 = m0n; m1 = m1n;

        float ls0 = 0.f, ls1 = 0.f;
        #pragma unroll
        for (int nt = 0; nt < 8; nt++) {
            sa[nt][0] = __expf(sa[nt][0] - m0n);
            sa[nt][1] = __expf(sa[nt][1] - m0n);
            sa[nt][2] = __expf(sa[nt][2] - m1n);
            sa[nt][3] = __expf(sa[nt][3] - m1n);
            ls0 += sa[nt][0] + sa[nt][1];
            ls1 += sa[nt][2] + sa[nt][3];
        }
        ls0 += __shfl_xor_sync(0xffffffffu, ls0, 1);
        ls0 += __shfl_xor_sync(0xffffffffu, ls0, 2);
        ls1 += __shfl_xor_sync(0xffffffffu, ls1, 1);
        ls1 += __shfl_xor_sync(0xffffffffu, ls1, 2);
        l0 = l0 * cr0 + ls0;
        l1 = l1 * cr1 + ls1;

        #pragma unroll
        for (int nt = 0; nt < 8; nt++) {
            oacc[nt][0] *= cr0; oacc[nt][1] *= cr0;
            oacc[nt][2] *= cr1; oacc[nt][3] *= cr1;
        }

        #pragma unroll
        for (int ks = 0; ks < 4; ks++) {
            const unsigned a0 = packh2(sa[2*ks  ][0], sa[2*ks  ][1]);
            const unsigned a1 = packh2(sa[2*ks  ][2], sa[2*ks  ][3]);
            const unsigned a2 = packh2(sa[2*ks+1][0], sa[2*ks+1][1]);
            const unsigned a3 = packh2(sa[2*ks+1][2], sa[2*ks+1][3]);
            #pragma unroll
            for (int dg = 0; dg < 4; dg++) {
                unsigned v0, v1, v2, v3;
                LDSM_X4T(v0, v1, v2, v3, v_frag + bo + (ks * 16 * AP + dg * 16) * 2);
                mma_f16(oacc[2*dg    ], a0, a1, a2, a3, v0, v1);
                mma_f16(oacc[2*dg + 1], a0, a1, a2, a3, v2, v3);
            }
        }

        __syncthreads();
        if (kb + 2 < nkb) issue_tile(kb + 2, buf);
        CP_COMMIT();
    }

    const float inv0 = 1.f / l0;
    const float inv1 = 1.f / l1;
    float* op = O + ((size_t)(b * S_ + row0)) * DM + h * DH;
    #pragma unroll
    for (int nt = 0; nt < 8; nt++) {
        float2 v;
        v.x = oacc[nt][0] * inv0; v.y = oacc[nt][1] * inv0;
        *(float2*)&op[nt * 8 + 2 * t] = v;
        v.x = oacc[nt][2] * inv1; v.y = oacc[nt][3] * inv1;
        *(float2*)&op[(size_t)8 * DM + nt * 8 + 2 * t] = v;
    }
}

// ---------------- residual add + layernorm (fp32 out + fp16 copy) --------
__global__ __launch_bounds__(256)
void ln_kernel(const float* __restrict__ att, const float* __restrict__ resid,
               const float* __restrict__ g, const float* __restrict__ bt,
               float* __restrict__ xout, __half* __restrict__ xh)
{
    const int row = blockIdx.x;
    const int tid = threadIdx.x;

    float4 a = *(const float4*)&att  [(size_t)row * DM + tid * 4];
    float4 r = *(const float4*)&resid[(size_t)row * DM + tid * 4];
    float4 v;
    v.x = a.x + r.x; v.y = a.y + r.y; v.z = a.z + r.z; v.w = a.w + r.w;

    float s1 = v.x + v.y + v.z + v.w;
    float s2 = v.x*v.x + v.y*v.y + v.z*v.z + v.w*v.w;

    __shared__ float sh1[8], sh2[8];
    #pragma unroll
    for (int o = 16; o > 0; o >>= 1) {
        s1 += __shfl_xor_sync(0xffffffffu, s1, o);
        s2 += __shfl_xor_sync(0xffffffffu, s2, o);
    }
    if ((tid & 31) == 0) { sh1[tid >> 5] = s1; sh2[tid >> 5] = s2; }
    __syncthreads();
    float t1 = 0.f, t2 = 0.f;
    #pragma unroll
    for (int i = 0; i < 8; i++) { t1 += sh1[i]; t2 += sh2[i]; }

    const float mu  = t1 * (1.0f / DM);
    const float var = t2 * (1.0f / DM) - mu * mu;
    const float rs  = rsqrtf(var + 1e-5f);

    float4 gg = *(const float4*)&g [tid * 4];
    float4 bb = *(const float4*)&bt[tid * 4];
    float4 o;
    o.x = (v.x - mu) * rs * gg.x + bb.x;
    o.y = (v.y - mu) * rs * gg.y + bb.y;
    o.z = (v.z - mu) * rs * gg.z + bb.z;
    o.w = (v.w - mu) * rs * gg.w + bb.w;
    *(float4*)&xout[(size_t)row * DM + tid * 4] = o;
    uint2 hh;
    hh.x = packh2(o.x, o.y);
    hh.y = packh2(o.z, o.w);
    *(uint2*)&xh[(size_t)row * DM + tid * 4] = hh;
}

// ---------------- launch ---------------------------------------------------
extern "C" void kernel_launch(void* const* d_in, const int* in_sizes, int n_in,
                              void* d_out, int out_size)
{
    const float* q    = (const float*)d_in[0];
    const float* k    = (const float*)d_in[1];
    const float* Wq   = (const float*)d_in[2];
    const float* bq   = (const float*)d_in[3];
    const float* Wk   = (const float*)d_in[4];
    const float* bk   = (const float*)d_in[5];
    const float* Wv   = (const float*)d_in[6];
    const float* bv   = (const float*)d_in[7];
    const float* W1   = (const float*)d_in[8];
    const float* b1   = (const float*)d_in[9];
    const float* W2   = (const float*)d_in[10];
    const float* b2   = (const float*)d_in[11];
    const float* ln_g = (const float*)d_in[12];
    const float* ln_b = (const float*)d_in[13];
    const int*   msk  = (const int*)d_in[14];

    __half *q16, *k16, *wq16, *wk16, *wv16, *w116, *w216, *Qh, *Kh, *Vh, *Xh, *Hh;
    float *Ab, *Xb;
    cudaGetSymbolAddress((void**)&q16,  g_q16);
    cudaGetSymbolAddress((void**)&k16,  g_k16);
    cudaGetSymbolAddress((void**)&wq16, g_wq16);
    cudaGetSymbolAddress((void**)&wk16, g_wk16);
    cudaGetSymbolAddress((void**)&wv16, g_wv16);
    cudaGetSymbolAddress((void**)&w116, g_w116);
    cudaGetSymbolAddress((void**)&w216, g_w216);
    cudaGetSymbolAddress((void**)&Qh,   g_Qh);
    cudaGetSymbolAddress((void**)&Kh,   g_Kh);
    cudaGetSymbolAddress((void**)&Vh,   g_Vh);
    cudaGetSymbolAddress((void**)&Xh,   g_Xh);
    cudaGetSymbolAddress((void**)&Hh,   g_Hh);
    cudaGetSymbolAddress((void**)&Ab,   g_att);
    cudaGetSymbolAddress((void**)&Xb,   g_x);

    cudaFuncSetAttribute(gemm16<1>, cudaFuncAttributeMaxDynamicSharedMemorySize, GSMEM);
    cudaFuncSetAttribute(gemm16<2>, cudaFuncAttributeMaxDynamicSharedMemorySize, GSMEM);
    cudaFuncSetAttribute(gemm_qkv,  cudaFuncAttributeMaxDynamicSharedMemorySize, GSMEM);

    // fused fp32 -> fp16 conversion pass
    f2h_all<<<19456, 256>>>((const float4*)q,  (const float4*)k,
                            (const float4*)Wq, (const float4*)Wk,
                            (const float4*)Wv, (const float4*)W1,
                            (const float4*)W2,
                            (uint2*)q16, (uint2*)k16, (uint2*)wq16,
                            (uint2*)wk16, (uint2*)wv16, (uint2*)w116,
                            (uint2*)w216);

    // merged QKV projections (one launch, grid.z selects which)
    gemm_qkv<<<dim3(DM / 128, MTOK / 128, 3), 128, GSMEM>>>(
        q16, k16, wq16, wk16, wv16, bq, bk, bv, Qh, Kh, Vh);

    // causal attention (fp16 in, fp32 out)
    attn_tc<<<dim3(S_ / 64, H_, B_), 128>>>(Qh, Kh, Vh, Ab, msk);

    // residual + layernorm (fp32 + fp16 outputs)
    ln_kernel<<<MTOK, 256>>>(Ab, q, ln_g, ln_b, Xb, Xh);

    // FFN
    gemm16<1><<<dim3(DFF / 128, MTOK / 128), 128, GSMEM>>>(Xh, w116, b1, Hh, nullptr, MTOK, DFF, DM);
    gemm16<2><<<dim3(DM / 128, MTOK / 128), 128, GSMEM>>>(Hh, w216, b2, d_out, Xb, MTOK, DM, DFF);
}